// round 2
// baseline (speedup 1.0000x reference)
#include <cuda_runtime.h>
#include <math.h>

static constexpr int BATCH = 4;
static constexpr int MG = 4;           // aligned groups
static constexpr int C = 32;
static constexpr int S = 32 * 32 * 32; // spatial voxels
static constexpr float SCALE = 0.17677669529663687f; // 1/sqrt(32)

// ---------------- device scratch (no runtime allocation allowed) --------------
__device__ float g_u[4 * C * S];       // u_j[c,s] for j=0..3 (batch-independent)
__device__ float g_vt[C * S];          // Wv4 @ token
__device__ float g_l4[S];              // logit of token-vs-token (batch-independent)
__device__ float g_h[BATCH * 64 * S];  // conv1+gelu intermediate
__device__ float g_wt1[128 * 125 * 64];// conv1 weights transposed [cin][tap][co]
__device__ float g_wt2[64 * 125 * 32]; // conv2 weights transposed

// ---------------- weight transpose: [co][cin][tap] -> [cin][tap][co] ----------
__global__ void k_wt(const float* __restrict__ w, float* __restrict__ wt,
                     int cinN, int coN) {
    int n = cinN * 125 * coN;
    for (int i = blockIdx.x * blockDim.x + threadIdx.x; i < n;
         i += gridDim.x * blockDim.x) {
        int co  = i % coN;
        int tap = (i / coN) % 125;
        int cin = i / (coN * 125);
        wt[i] = w[(co * cinN + cin) * 125 + tap];
    }
}

// ---------------- K1: batch-independent attention precompute ------------------
__global__ void k_pre(const float* __restrict__ basis, const float* __restrict__ mixer,
                      const float* __restrict__ wq, const float* __restrict__ wk,
                      const float* __restrict__ wv) {
    __shared__ float smm[C * 8];
    __shared__ float smq[C * C];
    __shared__ float smk[5 * C * C];
    __shared__ float smv[C * C];
    int tid = threadIdx.x;
    for (int t = tid; t < C * 8; t += blockDim.x)     smm[t] = mixer[t];
    for (int t = tid; t < C * C; t += blockDim.x)     smq[t] = wq[4 * C * C + t];
    for (int t = tid; t < 5 * C * C; t += blockDim.x) smk[t] = wk[t];
    for (int t = tid; t < C * C; t += blockDim.x)     smv[t] = wv[4 * C * C + t];
    __syncthreads();

    int s = blockIdx.x * blockDim.x + tid;
    float br[8];
#pragma unroll
    for (int r = 0; r < 8; ++r) br[r] = basis[r * S + s];

    float tok[C];
#pragma unroll
    for (int c = 0; c < C; ++c) {
        float a = 0.f;
#pragma unroll
        for (int r = 0; r < 8; ++r) a += smm[c * 8 + r] * br[r];
        tok[c] = a;
    }
    float q4[C];
#pragma unroll
    for (int o = 0; o < C; ++o) {
        float a = 0.f;
        for (int c = 0; c < C; ++c) a += smq[o * C + c] * tok[c];
        q4[o] = a;
    }
    // u_j[c] = sum_o q4[o] * wk[j,o,c], j=0..3 stored; j=4 folded into logit4
    for (int j = 0; j < 4; ++j) {
        for (int c = 0; c < C; ++c) {
            float a = 0.f;
            for (int o = 0; o < C; ++o) a += q4[o] * smk[(j * C + o) * C + c];
            g_u[(j * C + c) * S + s] = a;
        }
    }
    float l4 = 0.f;
    for (int c = 0; c < C; ++c) {
        float a = 0.f;
        for (int o = 0; o < C; ++o) a += q4[o] * smk[(4 * C + o) * C + c];
        l4 += a * tok[c];
    }
    g_l4[s] = l4 * SCALE;

    for (int c = 0; c < C; ++c) {
        float a = 0.f;
        for (int cp = 0; cp < C; ++cp) a += smv[c * C + cp] * tok[cp];
        g_vt[c * S + s] = a;
    }
}

// ---------------- K2: per-(b,s) attention combine -> out = alpha * att --------
__global__ void k_attn(const float* __restrict__ x, const float* __restrict__ wv,
                       const float* __restrict__ alpha, float* __restrict__ out) {
    __shared__ float smwv[4 * C * C]; // [j][cp][c]
    int tid = threadIdx.x;
    for (int t = tid; t < 4 * C * C; t += blockDim.x) {
        int c  = t % C;
        int cp = (t / C) % C;
        int j  = t / (C * C);
        smwv[t] = wv[(j * C + c) * C + cp];
    }
    __syncthreads();

    int idx = blockIdx.x * blockDim.x + tid;
    int b = idx >> 15;
    int s = idx & (S - 1);
    const float* xb = x + (size_t)b * MG * C * S + s;

    float l[5];
    for (int j = 0; j < 4; ++j) {
        float a = 0.f;
        for (int c = 0; c < C; ++c)
            a += g_u[(j * C + c) * S + s] * xb[(j * C + c) * S];
        l[j] = a * SCALE;
    }
    l[4] = g_l4[s];

    float m = l[0];
#pragma unroll
    for (int j = 1; j < 5; ++j) m = fmaxf(m, l[j]);
    float p[5], sum = 0.f;
#pragma unroll
    for (int j = 0; j < 5; ++j) { p[j] = expf(l[j] - m); sum += p[j]; }
    float inv = 1.f / sum;
#pragma unroll
    for (int j = 0; j < 5; ++j) p[j] *= inv;

    float o_[C];
#pragma unroll
    for (int c = 0; c < C; ++c) o_[c] = p[4] * g_vt[c * S + s];
    for (int j = 0; j < 4; ++j) {
        for (int cp = 0; cp < C; ++cp) {
            float xv = p[j] * xb[(j * C + cp) * S];
            const float* wp = &smwv[(j * C + cp) * C];
#pragma unroll
            for (int c = 0; c < C; ++c) o_[c] += wp[c] * xv;
        }
    }
    float a0 = alpha[0];
#pragma unroll
    for (int c = 0; c < C; ++c)
        out[((size_t)b * C + c) * S + s] = a0 * o_[c];
}

// ---------------- 5x5x5 conv, pad 2. One block per (b,h,w), thread = cout ----
template <int CIN, int COUT, bool GELU, bool ACCUM>
__global__ void k_conv(const float* __restrict__ in, const float* __restrict__ wt,
                       const float* __restrict__ bias, float* __restrict__ out) {
    int w = blockIdx.x, h = blockIdx.y, b = blockIdx.z;
    int co = threadIdx.x;
    __shared__ float sx[5][36];
    float acc[32];
#pragma unroll
    for (int d = 0; d < 32; ++d) acc[d] = 0.f;

    for (int cin = 0; cin < CIN; ++cin) {
        const float* inch = in + (size_t)(b * CIN + cin) * S;
        for (int dh = 0; dh < 5; ++dh) {
            int ih = h + dh - 2;
            if ((unsigned)ih >= 32u) continue;   // uniform across block
            __syncthreads();
            for (int t = threadIdx.x; t < 180; t += COUT) {
                int ws = t / 36, dp = t - ws * 36;
                int iw = w + ws - 2, id = dp - 2;
                float v = 0.f;
                if ((unsigned)iw < 32u && (unsigned)id < 32u)
                    v = inch[ih * 1024 + iw * 32 + id];
                sx[ws][dp] = v;
            }
            __syncthreads();
            const float* wrow = wt + (cin * 125 + dh * 25) * COUT + co;
            for (int dw = 0; dw < 5; ++dw) {
                float xr[36];
#pragma unroll
                for (int t = 0; t < 36; ++t) xr[t] = sx[dw][t];
#pragma unroll
                for (int dd = 0; dd < 5; ++dd) {
                    float wval = wrow[(dw * 5 + dd) * COUT];
#pragma unroll
                    for (int d = 0; d < 32; ++d) acc[d] += xr[d + dd] * wval;
                }
            }
        }
    }
    float bs = bias[co];
    float* op = out + (((size_t)(b * COUT + co) * 32 + h) * 32 + w) * 32;
#pragma unroll
    for (int d = 0; d < 32; ++d) {
        float v = acc[d] + bs;
        if (GELU) v = 0.5f * v * (1.f + erff(v * 0.70710678118654752f));
        if (ACCUM) v += op[d];
        op[d] = v;
    }
}

// ------------------------------- launch ---------------------------------------
extern "C" void kernel_launch(void* const* d_in, const int* in_sizes, int n_in,
                              void* d_out, int out_size) {
    const float* x     = (const float*)d_in[0];
    const float* basis = (const float*)d_in[1];
    const float* mixer = (const float*)d_in[2];
    const float* wq    = (const float*)d_in[3];
    const float* wk    = (const float*)d_in[4];
    const float* wv    = (const float*)d_in[5];
    const float* c1w   = (const float*)d_in[6];
    const float* c1b   = (const float*)d_in[7];
    const float* c2w   = (const float*)d_in[8];
    const float* c2b   = (const float*)d_in[9];
    const float* alpha = (const float*)d_in[10];
    float* out = (float*)d_out;

    float *wt1, *wt2, *hbuf;
    cudaGetSymbolAddress((void**)&wt1, g_wt1);
    cudaGetSymbolAddress((void**)&wt2, g_wt2);
    cudaGetSymbolAddress((void**)&hbuf, g_h);

    k_wt<<<256, 256>>>(c1w, wt1, 128, 64);
    k_wt<<<64, 256>>>(c2w, wt2, 64, 32);
    k_pre<<<S / 256, 256>>>(basis, mixer, wq, wk, wv);
    k_attn<<<(BATCH * S) / 256, 256>>>(x, wv, alpha, out);
    k_conv<128, 64, true, false><<<dim3(32, 32, 4), 64>>>(x, wt1, c1b, hbuf);
    k_conv<64, 32, false, true><<<dim3(32, 32, 4), 32>>>(hbuf, wt2, c2b, out);
}

// round 4
// speedup vs baseline: 1.9553x; 1.9553x over previous
#include <cuda_runtime.h>
#include <math.h>

static constexpr int BATCH = 4;
static constexpr int MG = 4;           // aligned groups
static constexpr int C = 32;
static constexpr int S = 32 * 32 * 32; // spatial voxels
static constexpr float SCALE = 0.17677669529663687f; // 1/sqrt(32)

// ---------------- device scratch (no runtime allocation allowed) --------------
__device__ float g_u[4 * C * S];       // u_j[c,s] for j=0..3 (batch-independent)
__device__ float g_vt[C * S];          // Wv4 @ token
__device__ float g_l4[S];              // token-vs-token logit (batch-independent)
__device__ float g_h[BATCH * 64 * S];  // conv1+gelu intermediate
__device__ float g_wt1[128 * 125 * 64];// conv1 weights transposed [cin][tap][co]
__device__ float g_wt2[64 * 125 * 32]; // conv2 weights transposed

// ---------------- weight transpose: [co][cin][tap] -> [cin][tap][co] ----------
__global__ void k_wt(const float* __restrict__ w, float* __restrict__ wt,
                     int cinN, int coN) {
    int n = cinN * 125 * coN;
    for (int i = blockIdx.x * blockDim.x + threadIdx.x; i < n;
         i += gridDim.x * blockDim.x) {
        int co  = i % coN;
        int tap = (i / coN) % 125;
        int cin = i / (coN * 125);
        wt[i] = w[(co * cinN + cin) * 125 + tap];
    }
}

// ---------------- K1: batch-independent attention precompute ------------------
__global__ void k_pre(const float* __restrict__ basis, const float* __restrict__ mixer,
                      const float* __restrict__ wq, const float* __restrict__ wk,
                      const float* __restrict__ wv) {
    __shared__ float smm[C * 8];
    __shared__ float smq[C * C];
    __shared__ float smk[5 * C * C];
    __shared__ float smv[C * C];
    int tid = threadIdx.x;
    for (int t = tid; t < C * 8; t += blockDim.x)     smm[t] = mixer[t];
    for (int t = tid; t < C * C; t += blockDim.x)     smq[t] = wq[4 * C * C + t];
    for (int t = tid; t < 5 * C * C; t += blockDim.x) smk[t] = wk[t];
    for (int t = tid; t < C * C; t += blockDim.x)     smv[t] = wv[4 * C * C + t];
    __syncthreads();

    int s = blockIdx.x * blockDim.x + tid;
    float br[8];
#pragma unroll
    for (int r = 0; r < 8; ++r) br[r] = basis[r * S + s];

    float tok[C];
#pragma unroll
    for (int c = 0; c < C; ++c) {
        float a = 0.f;
#pragma unroll
        for (int r = 0; r < 8; ++r) a += smm[c * 8 + r] * br[r];
        tok[c] = a;
    }
    float q4[C];
#pragma unroll
    for (int o = 0; o < C; ++o) {
        float a = 0.f;
        for (int c = 0; c < C; ++c) a += smq[o * C + c] * tok[c];
        q4[o] = a;
    }
    for (int j = 0; j < 4; ++j) {
        for (int c = 0; c < C; ++c) {
            float a = 0.f;
            for (int o = 0; o < C; ++o) a += q4[o] * smk[(j * C + o) * C + c];
            g_u[(j * C + c) * S + s] = a;
        }
    }
    float l4 = 0.f;
    for (int c = 0; c < C; ++c) {
        float a = 0.f;
        for (int o = 0; o < C; ++o) a += q4[o] * smk[(4 * C + o) * C + c];
        l4 += a * tok[c];
    }
    g_l4[s] = l4 * SCALE;

    for (int c = 0; c < C; ++c) {
        float a = 0.f;
        for (int cp = 0; cp < C; ++cp) a += smv[c * C + cp] * tok[cp];
        g_vt[c * S + s] = a;
    }
}

// ---------------- K2: per-(b,s) attention combine -> out = alpha * att --------
__global__ void k_attn(const float* __restrict__ x, const float* __restrict__ wv,
                       const float* __restrict__ alpha, float* __restrict__ out) {
    __shared__ float smwv[4 * C * C]; // [j][cp][c]
    int tid = threadIdx.x;
    for (int t = tid; t < 4 * C * C; t += blockDim.x) {
        int c  = t % C;
        int cp = (t / C) % C;
        int j  = t / (C * C);
        smwv[t] = wv[(j * C + c) * C + cp];
    }
    __syncthreads();

    int idx = blockIdx.x * blockDim.x + tid;
    int b = idx >> 15;
    int s = idx & (S - 1);
    const float* xb = x + (size_t)b * MG * C * S + s;

    float l[5];
    for (int j = 0; j < 4; ++j) {
        float a = 0.f;
        for (int c = 0; c < C; ++c)
            a += g_u[(j * C + c) * S + s] * xb[(j * C + c) * S];
        l[j] = a * SCALE;
    }
    l[4] = g_l4[s];

    float m = l[0];
#pragma unroll
    for (int j = 1; j < 5; ++j) m = fmaxf(m, l[j]);
    float p[5], sum = 0.f;
#pragma unroll
    for (int j = 0; j < 5; ++j) { p[j] = expf(l[j] - m); sum += p[j]; }
    float inv = 1.f / sum;
#pragma unroll
    for (int j = 0; j < 5; ++j) p[j] *= inv;

    float o_[C];
#pragma unroll
    for (int c = 0; c < C; ++c) o_[c] = p[4] * g_vt[c * S + s];
    for (int j = 0; j < 4; ++j) {
        for (int cp = 0; cp < C; ++cp) {
            float xv = p[j] * xb[(j * C + cp) * S];
            const float* wp = &smwv[(j * C + cp) * C];
#pragma unroll
            for (int c = 0; c < C; ++c) o_[c] += wp[c] * xv;
        }
    }
    float a0 = alpha[0];
#pragma unroll
    for (int c = 0; c < C; ++c)
        out[((size_t)b * C + c) * S + s] = a0 * o_[c];
}

// ======================= tf32 tensor-core conv ================================
// Implicit GEMM: D[cout, (w,d)] += W[cout, cin] * X[cin, (w,d)] accumulated over
// 125 taps, k-chunks of 8 cin. Block = (w-tile, h, b); 256 threads = 8 warps,
// each warp owns one w position with tile m(COUT slice)=32 x n(d)=32.

__device__ __forceinline__ unsigned f2tf32(float v) {
    unsigned u;
    asm("cvt.rna.tf32.f32 %0, %1;" : "=r"(u) : "f"(v));
    return u;
}

__device__ __forceinline__ void mma_tf32(float* c, const unsigned* a,
                                         unsigned b0, unsigned b1) {
    asm volatile(
        "mma.sync.aligned.m16n8k8.row.col.f32.tf32.tf32.f32 "
        "{%0,%1,%2,%3}, {%4,%5,%6,%7}, {%8,%9}, {%0,%1,%2,%3};"
        : "+f"(c[0]), "+f"(c[1]), "+f"(c[2]), "+f"(c[3])
        : "r"(a[0]), "r"(a[1]), "r"(a[2]), "r"(a[3]), "r"(b0), "r"(b1));
}

// pick d-dim padding so the cin-stride of the X tile is ≡ 8 (mod 32) -> the
// 32 lanes of a B-fragment load (8*tig + gid pattern) hit 32 distinct banks.
__host__ __device__ constexpr int pick_pd(int iwt) {
    for (int p = 37; p < 64; ++p)
        if ((5 * iwt * p) % 32 == 8) return p;
    return 37;
}

template <int CIN, int COUT, int WT, int WM, bool GELU, bool ACCUM>
__global__ __launch_bounds__(256, 2)
void k_conv_tc(const float* __restrict__ in, const float* __restrict__ wt,
               const float* __restrict__ bias, float* __restrict__ out) {
    constexpr int WN  = 8 / WM;           // warps along n (= w positions/block)
    static_assert(WN == WT, "one w per n-warp");
    constexpr int MT  = COUT / (16 * WM); // m16-tiles per warp
    constexpr int NT  = 4;                // n8-tiles per warp (n = 32 d)
    constexpr int CP  = COUT + 8;         // padded cout (bank decorrelation)
    constexpr int IWT = WT + 4;           // w halo
    constexpr int PD  = pick_pd(IWT);     // padded d dim (36 valid + pad)
    constexpr int XN  = 8 * 5 * IWT * PD; // X tile elems (8 cin x 5 ih)
    constexpr int WEL = 8 * 25 * COUT;    // W tile elems per (cin-chunk, dh)
    constexpr int CSTRIDE = 5 * IWT * PD; // cin stride in X tile

    extern __shared__ unsigned smem_u[];
    unsigned* sx = smem_u;                 // [8][5][IWT][PD], tf32 bits
    unsigned* sw = smem_u + XN;            // [8][25][CP],     tf32 bits

    const int bw  = blockIdx.x;
    const int h   = blockIdx.y;
    const int b   = blockIdx.z;
    const int tid = threadIdx.x;
    const int lane = tid & 31, wid = tid >> 5;
    const int gid  = lane >> 2, tig = lane & 3;
    const int wm = wid % WM, wn = wid / WM;
    const int mb = wm * (MT * 16);

    float acc[MT][NT][4];
#pragma unroll
    for (int mt = 0; mt < MT; ++mt)
#pragma unroll
        for (int nt = 0; nt < NT; ++nt)
#pragma unroll
            for (int q = 0; q < 4; ++q) acc[mt][nt][q] = 0.f;

    const float* inb = in + (size_t)b * CIN * S;

    for (int cc = 0; cc < CIN / 8; ++cc) {
        __syncthreads();  // everyone done with previous X (and W)
        // ---- stage X tile: cin chunk of 8, 5 ih rows, halo in w,d; tf32 ----
        for (int idx = tid; idx < XN; idx += 256) {
            int ids = idx % PD;
            int r   = idx / PD;
            int iws = r % IWT; r /= IWT;
            int ihs = r % 5;
            int ci  = r / 5;
            int id = ids - 2, iw = bw * WT + iws - 2, ih = h + ihs - 2;
            float v = 0.f;
            if ((unsigned)id < 32u && (unsigned)iw < 32u && (unsigned)ih < 32u)
                v = inb[(size_t)(cc * 8 + ci) * S + ih * 1024 + iw * 32 + id];
            sx[idx] = f2tf32(v);
        }
        for (int dh = 0; dh < 5; ++dh) {
            __syncthreads();  // X visible / previous W use finished
            // ---- stage W tile: 8 cin x 25 (dw,dd) taps x COUT; tf32 ----
            for (int idx = tid; idx < WEL; idx += 256) {
                int co = idx % COUT;
                int r  = idx / COUT;
                int j  = r % 25;
                int ci = r / 25;
                sw[(ci * 25 + j) * CP + co] =
                    f2tf32(wt[((size_t)(cc * 8 + ci) * 125 + dh * 25 + j) * COUT + co]);
            }
            __syncthreads();  // W visible

            const unsigned* sxp = sx + ((tig * 5 + dh) * IWT + wn) * PD + gid;
            const unsigned* swp = sw + tig * 25 * CP + mb + gid;

#pragma unroll
            for (int dw = 0; dw < 5; ++dw) {
#pragma unroll
                for (int dd = 0; dd < 5; ++dd) {
                    const int j = dw * 5 + dd;
                    unsigned a[MT][4];
#pragma unroll
                    for (int mt = 0; mt < MT; ++mt) {
                        const unsigned* p = swp + j * CP + mt * 16;
                        a[mt][0] = p[0];               // row gid,   col tig
                        a[mt][1] = p[8];               // row gid+8, col tig
                        a[mt][2] = p[4 * 25 * CP];     // row gid,   col tig+4
                        a[mt][3] = p[4 * 25 * CP + 8]; // row gid+8, col tig+4
                    }
#pragma unroll
                    for (int nt = 0; nt < NT; ++nt) {
                        unsigned b0 = sxp[dw * PD + dd + nt * 8];
                        unsigned b1 = sxp[4 * CSTRIDE + dw * PD + dd + nt * 8];
#pragma unroll
                        for (int mt = 0; mt < MT; ++mt)
                            mma_tf32(acc[mt][nt], a[mt], b0, b1);
                    }
                }
            }
        }
    }

    // ---------------- epilogue: bias (+gelu) (+accum) ----------------
    const int w_out = bw * WT + wn;
#pragma unroll
    for (int mt = 0; mt < MT; ++mt) {
        const int co0 = mb + mt * 16 + gid;
        const float bs0 = bias[co0], bs1 = bias[co0 + 8];
#pragma unroll
        for (int nt = 0; nt < NT; ++nt) {
            const int d = nt * 8 + 2 * tig;
            float v[4];
            v[0] = acc[mt][nt][0] + bs0;
            v[1] = acc[mt][nt][1] + bs0;
            v[2] = acc[mt][nt][2] + bs1;
            v[3] = acc[mt][nt][3] + bs1;
            if (GELU) {
#pragma unroll
                for (int q = 0; q < 4; ++q)
                    v[q] = 0.5f * v[q] *
                           (1.f + erff(v[q] * 0.70710678118654752f));
            }
            float2* o0 = (float2*)(out +
                ((((size_t)b * COUT + co0) * 32 + h) * 32 + w_out) * 32 + d);
            float2* o1 = (float2*)(out +
                ((((size_t)b * COUT + co0 + 8) * 32 + h) * 32 + w_out) * 32 + d);
            if (ACCUM) {
                float2 e0 = *o0, e1 = *o1;
                v[0] += e0.x; v[1] += e0.y; v[2] += e1.x; v[3] += e1.y;
            }
            *o0 = make_float2(v[0], v[1]);
            *o1 = make_float2(v[2], v[3]);
        }
    }
}

// ------------------------------- launch ---------------------------------------
extern "C" void kernel_launch(void* const* d_in, const int* in_sizes, int n_in,
                              void* d_out, int out_size) {
    const float* x     = (const float*)d_in[0];
    const float* basis = (const float*)d_in[1];
    const float* mixer = (const float*)d_in[2];
    const float* wq    = (const float*)d_in[3];
    const float* wk    = (const float*)d_in[4];
    const float* wv    = (const float*)d_in[5];
    const float* c1w   = (const float*)d_in[6];
    const float* c1b   = (const float*)d_in[7];
    const float* c2w   = (const float*)d_in[8];
    const float* c2b   = (const float*)d_in[9];
    const float* alpha = (const float*)d_in[10];
    float* out = (float*)d_out;

    float *wt1, *wt2, *hbuf;
    cudaGetSymbolAddress((void**)&wt1, g_wt1);
    cudaGetSymbolAddress((void**)&wt2, g_wt2);
    cudaGetSymbolAddress((void**)&hbuf, g_h);

    // conv1: CIN=128, COUT=64, 4 w/block (WM=2): X 8*5*8*37 + W 8*25*72
    constexpr int SM1 = (8 * 5 * 8 * pick_pd(8) + 8 * 25 * 72) * 4;
    // conv2: CIN=64, COUT=32, 8 w/block (WM=1): X 8*5*12*PD + W 8*25*40
    constexpr int SM2 = (8 * 5 * 12 * pick_pd(12) + 8 * 25 * 40) * 4;

    cudaFuncSetAttribute((const void*)k_conv_tc<128, 64, 4, 2, true, false>,
                         cudaFuncAttributeMaxDynamicSharedMemorySize, SM1);
    cudaFuncSetAttribute((const void*)k_conv_tc<64, 32, 8, 1, false, true>,
                         cudaFuncAttributeMaxDynamicSharedMemorySize, SM2);

    k_wt<<<256, 256>>>(c1w, wt1, 128, 64);
    k_wt<<<64, 256>>>(c2w, wt2, 64, 32);
    k_pre<<<S / 256, 256>>>(basis, mixer, wq, wk, wv);
    k_attn<<<(BATCH * S) / 256, 256>>>(x, wv, alpha, out);
    k_conv_tc<128, 64, 4, 2, true, false>
        <<<dim3(8, 32, 4), 256, SM1>>>(x, wt1, c1b, hbuf);
    k_conv_tc<64, 32, 8, 1, false, true>
        <<<dim3(4, 32, 4), 256, SM2>>>(hbuf, wt2, c2b, out);
}

// round 5
// speedup vs baseline: 3.0110x; 1.5399x over previous
#include <cuda_runtime.h>
#include <math.h>

static constexpr int BATCH = 4;
static constexpr int MG = 4;           // aligned groups
static constexpr int C = 32;
static constexpr int S = 32 * 32 * 32; // spatial voxels
static constexpr float SCALE = 0.17677669529663687f; // 1/sqrt(32)

// ---------------- device scratch (no runtime allocation allowed) --------------
__device__ float g_u[4 * C * S];       // u_j[c,s] for j=0..3 (batch-independent)
__device__ float g_vt[C * S];          // Wv4 @ token
__device__ float g_l4[S];              // token-vs-token logit (batch-independent)
__device__ float g_h[BATCH * 64 * S];  // conv1+gelu intermediate
__device__ unsigned g_wtp1[128 * 125 * 64]; // conv1 W, fragment-permuted tf32 bits
__device__ unsigned g_wtp2[64 * 125 * 32];  // conv2 W, fragment-permuted tf32 bits

__device__ __forceinline__ unsigned f2tf32(float v) {
    unsigned u;
    asm("cvt.rna.tf32.f32 %0, %1;" : "=r"(u) : "f"(v));
    return u;
}

// ---------- weight permute: [co][cin][tap] -> [cc][dh][j][wm][mt][lane][q] ----
// Emits tf32 bits in the exact per-thread mma A-fragment order so conv staging
// is a contiguous uint4 copy and A-fragment LDS is a single conflict-free
// LDS.128 per (tap, mt).
template <int CIN, int COUT, int WM, int MT>
__global__ void k_wtp(const float* __restrict__ w, unsigned* __restrict__ wtp) {
    int n = CIN * 125 * COUT;
    for (int p = blockIdx.x * blockDim.x + threadIdx.x; p < n;
         p += gridDim.x * blockDim.x) {
        int q    = p & 3;
        int lane = (p >> 2) & 31;
        int r    = p >> 7;
        int mt = r % MT; r /= MT;
        int wm = r % WM; r /= WM;
        int j  = r % 25; r /= 25;
        int dh = r % 5;
        int cc = r / 5;
        int gid = lane >> 2, tig = lane & 3;
        int co  = wm * (MT * 16) + mt * 16 + gid + 8 * (q & 1);
        int k   = tig + 4 * (q >> 1);
        int cin = cc * 8 + k;
        int tap = dh * 25 + j;
        wtp[p] = f2tf32(w[((size_t)co * CIN + cin) * 125 + tap]);
    }
}

// ---------------- K1: batch-independent attention precompute ------------------
__global__ void k_pre(const float* __restrict__ basis, const float* __restrict__ mixer,
                      const float* __restrict__ wq, const float* __restrict__ wk,
                      const float* __restrict__ wv) {
    __shared__ float smm[C * 8];
    __shared__ float smq[C * C];
    __shared__ float smk[5 * C * C];
    __shared__ float smv[C * C];
    int tid = threadIdx.x;
    for (int t = tid; t < C * 8; t += blockDim.x)     smm[t] = mixer[t];
    for (int t = tid; t < C * C; t += blockDim.x)     smq[t] = wq[4 * C * C + t];
    for (int t = tid; t < 5 * C * C; t += blockDim.x) smk[t] = wk[t];
    for (int t = tid; t < C * C; t += blockDim.x)     smv[t] = wv[4 * C * C + t];
    __syncthreads();

    int s = blockIdx.x * blockDim.x + tid;
    float br[8];
#pragma unroll
    for (int r = 0; r < 8; ++r) br[r] = basis[r * S + s];

    float tok[C];
#pragma unroll
    for (int c = 0; c < C; ++c) {
        float a = 0.f;
#pragma unroll
        for (int r = 0; r < 8; ++r) a += smm[c * 8 + r] * br[r];
        tok[c] = a;
    }
    float q4[C];
#pragma unroll
    for (int o = 0; o < C; ++o) {
        float a = 0.f;
        for (int c = 0; c < C; ++c) a += smq[o * C + c] * tok[c];
        q4[o] = a;
    }
    for (int j = 0; j < 4; ++j) {
        for (int c = 0; c < C; ++c) {
            float a = 0.f;
            for (int o = 0; o < C; ++o) a += q4[o] * smk[(j * C + o) * C + c];
            g_u[(j * C + c) * S + s] = a;
        }
    }
    float l4 = 0.f;
    for (int c = 0; c < C; ++c) {
        float a = 0.f;
        for (int o = 0; o < C; ++o) a += q4[o] * smk[(4 * C + o) * C + c];
        l4 += a * tok[c];
    }
    g_l4[s] = l4 * SCALE;

    for (int c = 0; c < C; ++c) {
        float a = 0.f;
        for (int cp = 0; cp < C; ++cp) a += smv[c * C + cp] * tok[cp];
        g_vt[c * S + s] = a;
    }
}

// ---------------- K2: per-(b,s) attention combine -> out = alpha * att --------
__global__ void k_attn(const float* __restrict__ x, const float* __restrict__ wv,
                       const float* __restrict__ alpha, float* __restrict__ out) {
    __shared__ float smwv[4 * C * C]; // [j][cp][c]
    int tid = threadIdx.x;
    for (int t = tid; t < 4 * C * C; t += blockDim.x) {
        int c  = t % C;
        int cp = (t / C) % C;
        int j  = t / (C * C);
        smwv[t] = wv[(j * C + c) * C + cp];
    }
    __syncthreads();

    int idx = blockIdx.x * blockDim.x + tid;
    int b = idx >> 15;
    int s = idx & (S - 1);
    const float* xb = x + (size_t)b * MG * C * S + s;

    float l[5];
    for (int j = 0; j < 4; ++j) {
        float a = 0.f;
        for (int c = 0; c < C; ++c)
            a += g_u[(j * C + c) * S + s] * xb[(j * C + c) * S];
        l[j] = a * SCALE;
    }
    l[4] = g_l4[s];

    float m = l[0];
#pragma unroll
    for (int j = 1; j < 5; ++j) m = fmaxf(m, l[j]);
    float p[5], sum = 0.f;
#pragma unroll
    for (int j = 0; j < 5; ++j) { p[j] = expf(l[j] - m); sum += p[j]; }
    float inv = 1.f / sum;
#pragma unroll
    for (int j = 0; j < 5; ++j) p[j] *= inv;

    float o_[C];
#pragma unroll
    for (int c = 0; c < C; ++c) o_[c] = p[4] * g_vt[c * S + s];
    for (int j = 0; j < 4; ++j) {
        for (int cp = 0; cp < C; ++cp) {
            float xv = p[j] * xb[(j * C + cp) * S];
            const float* wp = &smwv[(j * C + cp) * C];
#pragma unroll
            for (int c = 0; c < C; ++c) o_[c] += wp[c] * xv;
        }
    }
    float a0 = alpha[0];
#pragma unroll
    for (int c = 0; c < C; ++c)
        out[((size_t)b * C + c) * S + s] = a0 * o_[c];
}

// ======================= tf32 tensor-core conv ================================

__device__ __forceinline__ void mma_tf32(float* c, const unsigned* a,
                                         unsigned b0, unsigned b1) {
    asm volatile(
        "mma.sync.aligned.m16n8k8.row.col.f32.tf32.tf32.f32 "
        "{%0,%1,%2,%3}, {%4,%5,%6,%7}, {%8,%9}, {%0,%1,%2,%3};"
        : "+f"(c[0]), "+f"(c[1]), "+f"(c[2]), "+f"(c[3])
        : "r"(a[0]), "r"(a[1]), "r"(a[2]), "r"(a[3]), "r"(b0), "r"(b1));
}

// pick d-dim padding so the cin-stride of the X tile is ≡ 8 (mod 32) -> the
// 32 lanes of a B-fragment load hit 32 distinct banks.
__host__ __device__ constexpr int pick_pd(int iwt) {
    for (int p = 37; p < 64; ++p)
        if ((5 * iwt * p) % 32 == 8) return p;
    return 37;
}

template <int CIN, int COUT, int WT, int WM, bool GELU, bool ACCUM>
__global__ __launch_bounds__(256, 2)
void k_conv_tc(const float* __restrict__ in, const unsigned* __restrict__ wtp,
               const float* __restrict__ bias, float* __restrict__ out) {
    constexpr int WN  = 8 / WM;           // warps along n (= w positions/block)
    static_assert(WN == WT, "one w per n-warp");
    constexpr int MT  = COUT / (16 * WM); // m16-tiles per warp
    constexpr int NT  = 4;                // n8-tiles per warp (n = 32 d)
    constexpr int IWT = WT + 4;           // w halo
    constexpr int PD  = pick_pd(IWT);     // padded d dim (36 valid + pad)
    constexpr int XN  = 8 * 5 * IWT * PD; // X tile elems (8 cin x 5 ih)
    constexpr int WEL = 25 * WM * MT * 128; // W frag elems per (cin-chunk, dh)
    constexpr int CSTRIDE = 5 * IWT * PD; // cin stride in X tile

    extern __shared__ unsigned smem_u[];
    unsigned* sx = smem_u;                 // [8][5][IWT][PD], tf32 bits
    uint4*    sw4 = (uint4*)(smem_u + XN); // [25][WM][MT][32] uint4 fragments

    const int bw  = blockIdx.x;
    const int h   = blockIdx.y;
    const int b   = blockIdx.z;
    const int tid = threadIdx.x;
    const int lane = tid & 31, wid = tid >> 5;
    const int gid  = lane >> 2, tig = lane & 3;
    const int wm = wid % WM, wn = wid / WM;
    const int mb = wm * (MT * 16);

    float acc[MT][NT][4];
#pragma unroll
    for (int mt = 0; mt < MT; ++mt)
#pragma unroll
        for (int nt = 0; nt < NT; ++nt)
#pragma unroll
            for (int q = 0; q < 4; ++q) acc[mt][nt][q] = 0.f;

    const float* inb = in + (size_t)b * CIN * S;

    for (int cc = 0; cc < CIN / 8; ++cc) {
        __syncthreads();  // everyone done with previous X (and W)
        // ---- stage X tile: cin chunk of 8, 5 ih rows, halo in w,d; tf32 ----
        for (int idx = tid; idx < XN; idx += 256) {
            int ids = idx % PD;
            int r   = idx / PD;
            int iws = r % IWT; r /= IWT;
            int ihs = r % 5;
            int ci  = r / 5;
            int id = ids - 2, iw = bw * WT + iws - 2, ih = h + ihs - 2;
            float v = 0.f;
            if ((unsigned)id < 32u && (unsigned)iw < 32u && (unsigned)ih < 32u)
                v = inb[(size_t)(cc * 8 + ci) * S + ih * 1024 + iw * 32 + id];
            sx[idx] = f2tf32(v);
        }
        for (int dh = 0; dh < 5; ++dh) {
            __syncthreads();  // X visible / previous W use finished
            // ---- stage W fragments: contiguous coalesced uint4 copy ----
            const uint4* wsrc = (const uint4*)(wtp + (size_t)(cc * 5 + dh) * WEL);
#pragma unroll
            for (int idx = tid; idx < WEL / 4; idx += 256)
                sw4[idx] = wsrc[idx];
            __syncthreads();  // W visible

            const unsigned* sxp = sx + ((tig * 5 + dh) * IWT + wn) * PD + gid;
            const uint4* swp = sw4 + wm * MT * 32 + lane;

#pragma unroll
            for (int dw = 0; dw < 5; ++dw) {
#pragma unroll
                for (int dd = 0; dd < 5; ++dd) {
                    const int j = dw * 5 + dd;
                    uint4 a[MT];
#pragma unroll
                    for (int mt = 0; mt < MT; ++mt)
                        a[mt] = swp[(j * WM * MT + mt) * 32];
#pragma unroll
                    for (int nt = 0; nt < NT; ++nt) {
                        unsigned b0 = sxp[dw * PD + dd + nt * 8];
                        unsigned b1 = sxp[4 * CSTRIDE + dw * PD + dd + nt * 8];
#pragma unroll
                        for (int mt = 0; mt < MT; ++mt)
                            mma_tf32(acc[mt][nt], (const unsigned*)&a[mt], b0, b1);
                    }
                }
            }
        }
    }

    // ---------------- epilogue: bias (+gelu) (+accum) ----------------
    const int w_out = bw * WT + wn;
#pragma unroll
    for (int mt = 0; mt < MT; ++mt) {
        const int co0 = mb + mt * 16 + gid;
        const float bs0 = bias[co0], bs1 = bias[co0 + 8];
#pragma unroll
        for (int nt = 0; nt < NT; ++nt) {
            const int d = nt * 8 + 2 * tig;
            float v[4];
            v[0] = acc[mt][nt][0] + bs0;
            v[1] = acc[mt][nt][1] + bs0;
            v[2] = acc[mt][nt][2] + bs1;
            v[3] = acc[mt][nt][3] + bs1;
            if (GELU) {
#pragma unroll
                for (int q = 0; q < 4; ++q)
                    v[q] = 0.5f * v[q] *
                           (1.f + erff(v[q] * 0.70710678118654752f));
            }
            float2* o0 = (float2*)(out +
                ((((size_t)b * COUT + co0) * 32 + h) * 32 + w_out) * 32 + d);
            float2* o1 = (float2*)(out +
                ((((size_t)b * COUT + co0 + 8) * 32 + h) * 32 + w_out) * 32 + d);
            if (ACCUM) {
                float2 e0 = *o0, e1 = *o1;
                v[0] += e0.x; v[1] += e0.y; v[2] += e1.x; v[3] += e1.y;
            }
            *o0 = make_float2(v[0], v[1]);
            *o1 = make_float2(v[2], v[3]);
        }
    }
}

// ------------------------------- launch ---------------------------------------
extern "C" void kernel_launch(void* const* d_in, const int* in_sizes, int n_in,
                              void* d_out, int out_size) {
    const float* x     = (const float*)d_in[0];
    const float* basis = (const float*)d_in[1];
    const float* mixer = (const float*)d_in[2];
    const float* wq    = (const float*)d_in[3];
    const float* wk    = (const float*)d_in[4];
    const float* wv    = (const float*)d_in[5];
    const float* c1w   = (const float*)d_in[6];
    const float* c1b   = (const float*)d_in[7];
    const float* c2w   = (const float*)d_in[8];
    const float* c2b   = (const float*)d_in[9];
    const float* alpha = (const float*)d_in[10];
    float* out = (float*)d_out;

    unsigned *wtp1, *wtp2;
    float *hbuf;
    cudaGetSymbolAddress((void**)&wtp1, g_wtp1);
    cudaGetSymbolAddress((void**)&wtp2, g_wtp2);
    cudaGetSymbolAddress((void**)&hbuf, g_h);

    // conv1: CIN=128, COUT=64, WT=4, WM=2: X 8*5*8*37 + Wfrag 25*2*2*128
    constexpr int SM1 = (8 * 5 * 8 * pick_pd(8) + 25 * 2 * 2 * 128) * 4;
    // conv2: CIN=64, COUT=32, WT=8, WM=1: X 8*5*12*38 + Wfrag 25*1*2*128
    constexpr int SM2 = (8 * 5 * 12 * pick_pd(12) + 25 * 1 * 2 * 128) * 4;

    cudaFuncSetAttribute((const void*)k_conv_tc<128, 64, 4, 2, true, false>,
                         cudaFuncAttributeMaxDynamicSharedMemorySize, SM1);
    cudaFuncSetAttribute((const void*)k_conv_tc<64, 32, 8, 1, false, true>,
                         cudaFuncAttributeMaxDynamicSharedMemorySize, SM2);

    k_wtp<128, 64, 2, 2><<<256, 256>>>(c1w, wtp1);
    k_wtp<64, 32, 1, 2><<<64, 256>>>(c2w, wtp2);
    k_pre<<<S / 256, 256>>>(basis, mixer, wq, wk, wv);
    k_attn<<<(BATCH * S) / 256, 256>>>(x, wv, alpha, out);
    k_conv_tc<128, 64, 4, 2, true, false>
        <<<dim3(8, 32, 4), 256, SM1>>>(x, wtp1, c1b, hbuf);
    k_conv_tc<64, 32, 8, 1, false, true>
        <<<dim3(4, 32, 4), 256, SM2>>>(hbuf, wtp2, c2b, out);
}

// round 6
// speedup vs baseline: 3.0286x; 1.0058x over previous
#include <cuda_runtime.h>
#include <math.h>

static constexpr int BATCH = 4;
static constexpr int MG = 4;           // aligned groups
static constexpr int C = 32;
static constexpr int S = 32 * 32 * 32; // spatial voxels
static constexpr float SCALE = 0.17677669529663687f; // 1/sqrt(32)

// ---------------- device scratch (no runtime allocation allowed) --------------
__device__ float g_u[4 * C * S];       // u_j[c,s] for j=0..3 (batch-independent)
__device__ float g_vt[C * S];          // Wv4 @ token
__device__ float g_l4[S];              // token-vs-token logit (batch-independent)
__device__ float g_h[BATCH * 64 * S];  // conv1+gelu intermediate
__device__ unsigned g_wtp1[128 * 125 * 64]; // conv1 W, fragment-permuted tf32 bits
__device__ unsigned g_wtp2[64 * 125 * 32];  // conv2 W, fragment-permuted tf32 bits

__device__ __forceinline__ unsigned f2tf32(float v) {
    unsigned u;
    asm("cvt.rna.tf32.f32 %0, %1;" : "=r"(u) : "f"(v));
    return u;
}

// ---------- weight permute: [co][cin][tap] -> [cc][dh][j][wm][mt][lane][q] ----
// Emits tf32 bits in the exact per-thread mma A-fragment order so conv staging
// is a contiguous uint4 copy and A-fragment LDS is a single conflict-free
// LDS.128 per (tap, mt).
template <int CIN, int COUT, int WM, int MT>
__global__ void k_wtp(const float* __restrict__ w, unsigned* __restrict__ wtp) {
    int n = CIN * 125 * COUT;
    for (int p = blockIdx.x * blockDim.x + threadIdx.x; p < n;
         p += gridDim.x * blockDim.x) {
        int q    = p & 3;
        int lane = (p >> 2) & 31;
        int r    = p >> 7;
        int mt = r % MT; r /= MT;
        int wm = r % WM; r /= WM;
        int j  = r % 25; r /= 25;
        int dh = r % 5;
        int cc = r / 5;
        int gid = lane >> 2, tig = lane & 3;
        int co  = wm * (MT * 16) + mt * 16 + gid + 8 * (q & 1);
        int k   = tig + 4 * (q >> 1);
        int cin = cc * 8 + k;
        int tap = dh * 25 + j;
        wtp[p] = f2tf32(w[((size_t)co * CIN + cin) * 125 + tap]);
    }
}

// ---------------- K1: batch-independent attention precompute ------------------
__global__ void k_pre(const float* __restrict__ basis, const float* __restrict__ mixer,
                      const float* __restrict__ wq, const float* __restrict__ wk,
                      const float* __restrict__ wv) {
    __shared__ float smm[C * 8];
    __shared__ float smq[C * C];
    __shared__ float smk[5 * C * C];
    __shared__ float smv[C * C];
    int tid = threadIdx.x;
    for (int t = tid; t < C * 8; t += blockDim.x)     smm[t] = mixer[t];
    for (int t = tid; t < C * C; t += blockDim.x)     smq[t] = wq[4 * C * C + t];
    for (int t = tid; t < 5 * C * C; t += blockDim.x) smk[t] = wk[t];
    for (int t = tid; t < C * C; t += blockDim.x)     smv[t] = wv[4 * C * C + t];
    __syncthreads();

    int s = blockIdx.x * blockDim.x + tid;
    float br[8];
#pragma unroll
    for (int r = 0; r < 8; ++r) br[r] = basis[r * S + s];

    float tok[C];
#pragma unroll
    for (int c = 0; c < C; ++c) {
        float a = 0.f;
#pragma unroll
        for (int r = 0; r < 8; ++r) a += smm[c * 8 + r] * br[r];
        tok[c] = a;
    }
    float q4[C];
#pragma unroll
    for (int o = 0; o < C; ++o) {
        float a = 0.f;
        for (int c = 0; c < C; ++c) a += smq[o * C + c] * tok[c];
        q4[o] = a;
    }
    for (int j = 0; j < 4; ++j) {
        for (int c = 0; c < C; ++c) {
            float a = 0.f;
            for (int o = 0; o < C; ++o) a += q4[o] * smk[(j * C + o) * C + c];
            g_u[(j * C + c) * S + s] = a;
        }
    }
    float l4 = 0.f;
    for (int c = 0; c < C; ++c) {
        float a = 0.f;
        for (int o = 0; o < C; ++o) a += q4[o] * smk[(4 * C + o) * C + c];
        l4 += a * tok[c];
    }
    g_l4[s] = l4 * SCALE;

    for (int c = 0; c < C; ++c) {
        float a = 0.f;
        for (int cp = 0; cp < C; ++cp) a += smv[c * C + cp] * tok[cp];
        g_vt[c * S + s] = a;
    }
}

// ---------------- K2: per-(b,s) attention combine -> out = alpha * att --------
__global__ void k_attn(const float* __restrict__ x, const float* __restrict__ wv,
                       const float* __restrict__ alpha, float* __restrict__ out) {
    __shared__ float smwv[4 * C * C]; // [j][cp][c]
    int tid = threadIdx.x;
    for (int t = tid; t < 4 * C * C; t += blockDim.x) {
        int c  = t % C;
        int cp = (t / C) % C;
        int j  = t / (C * C);
        smwv[t] = wv[(j * C + c) * C + cp];
    }
    __syncthreads();

    int idx = blockIdx.x * blockDim.x + tid;
    int b = idx >> 15;
    int s = idx & (S - 1);
    const float* xb = x + (size_t)b * MG * C * S + s;

    float l[5];
    for (int j = 0; j < 4; ++j) {
        float a = 0.f;
        for (int c = 0; c < C; ++c)
            a += g_u[(j * C + c) * S + s] * xb[(j * C + c) * S];
        l[j] = a * SCALE;
    }
    l[4] = g_l4[s];

    float m = l[0];
#pragma unroll
    for (int j = 1; j < 5; ++j) m = fmaxf(m, l[j]);
    float p[5], sum = 0.f;
#pragma unroll
    for (int j = 0; j < 5; ++j) { p[j] = expf(l[j] - m); sum += p[j]; }
    float inv = 1.f / sum;
#pragma unroll
    for (int j = 0; j < 5; ++j) p[j] *= inv;

    float o_[C];
#pragma unroll
    for (int c = 0; c < C; ++c) o_[c] = p[4] * g_vt[c * S + s];
    for (int j = 0; j < 4; ++j) {
        for (int cp = 0; cp < C; ++cp) {
            float xv = p[j] * xb[(j * C + cp) * S];
            const float* wp = &smwv[(j * C + cp) * C];
#pragma unroll
            for (int c = 0; c < C; ++c) o_[c] += wp[c] * xv;
        }
    }
    float a0 = alpha[0];
#pragma unroll
    for (int c = 0; c < C; ++c)
        out[((size_t)b * C + c) * S + s] = a0 * o_[c];
}

// ======================= tf32 tensor-core conv ================================

__device__ __forceinline__ void mma_tf32(float* c, const unsigned* a,
                                         unsigned b0, unsigned b1) {
    asm volatile(
        "mma.sync.aligned.m16n8k8.row.col.f32.tf32.tf32.f32 "
        "{%0,%1,%2,%3}, {%4,%5,%6,%7}, {%8,%9}, {%0,%1,%2,%3};"
        : "+f"(c[0]), "+f"(c[1]), "+f"(c[2]), "+f"(c[3])
        : "r"(a[0]), "r"(a[1]), "r"(a[2]), "r"(a[3]), "r"(b0), "r"(b1));
}

// pick d-dim padding so the cin-stride of the X tile is ≡ 8 (mod 32) -> the
// 32 lanes of a B-fragment load hit 32 distinct banks.
__host__ __device__ constexpr int pick_pd(int iwt) {
    for (int p = 37; p < 64; ++p)
        if ((5 * iwt * p) % 32 == 8) return p;
    return 37;
}

template <int CIN, int COUT, int WT, int WM, bool GELU, bool ACCUM>
__global__ __launch_bounds__(256, 2)
void k_conv_tc(const float* __restrict__ in, const unsigned* __restrict__ wtp,
               const float* __restrict__ bias, float* __restrict__ out) {
    constexpr int WN  = 8 / WM;           // warps along n (= w positions/block)
    static_assert(WN == WT, "one w per n-warp");
    constexpr int MT  = COUT / (16 * WM); // m16-tiles per warp
    constexpr int NT  = 4;                // n8-tiles per warp (n = 32 d)
    constexpr int IWT = WT + 4;           // w halo
    constexpr int PD  = pick_pd(IWT);     // padded d dim (36 valid + pad)
    constexpr int XN  = 8 * 5 * IWT * PD; // X tile elems (8 cin x 5 ih)
    constexpr int WEL = 25 * WM * MT * 128; // W frag elems per (cin-chunk, dh)
    constexpr int CSTRIDE = 5 * IWT * PD; // cin stride in X tile

    extern __shared__ unsigned smem_u[];
    unsigned* sx = smem_u;                 // [8][5][IWT][PD], tf32 bits
    uint4*    sw4 = (uint4*)(smem_u + XN); // [25][WM][MT][32] uint4 fragments

    const int bw  = blockIdx.x;
    const int h   = blockIdx.y;
    const int b   = blockIdx.z;
    const int tid = threadIdx.x;
    const int lane = tid & 31, wid = tid >> 5;
    const int gid  = lane >> 2, tig = lane & 3;
    const int wm = wid % WM, wn = wid / WM;
    const int mb = wm * (MT * 16);

    float acc[MT][NT][4];
#pragma unroll
    for (int mt = 0; mt < MT; ++mt)
#pragma unroll
        for (int nt = 0; nt < NT; ++nt)
#pragma unroll
            for (int q = 0; q < 4; ++q) acc[mt][nt][q] = 0.f;

    const float* inb = in + (size_t)b * CIN * S;

    for (int cc = 0; cc < CIN / 8; ++cc) {
        __syncthreads();  // everyone done with previous X (and W)
        // ---- stage X tile: cin chunk of 8, 5 ih rows, halo in w,d; tf32 ----
        for (int idx = tid; idx < XN; idx += 256) {
            int ids = idx % PD;
            int r   = idx / PD;
            int iws = r % IWT; r /= IWT;
            int ihs = r % 5;
            int ci  = r / 5;
            int id = ids - 2, iw = bw * WT + iws - 2, ih = h + ihs - 2;
            float v = 0.f;
            if ((unsigned)id < 32u && (unsigned)iw < 32u && (unsigned)ih < 32u)
                v = inb[(size_t)(cc * 8 + ci) * S + ih * 1024 + iw * 32 + id];
            sx[idx] = f2tf32(v);
        }
        for (int dh = 0; dh < 5; ++dh) {
            __syncthreads();  // X visible / previous W use finished
            // ---- stage W fragments: contiguous coalesced uint4 copy ----
            const uint4* wsrc = (const uint4*)(wtp + (size_t)(cc * 5 + dh) * WEL);
#pragma unroll
            for (int idx = tid; idx < WEL / 4; idx += 256)
                sw4[idx] = wsrc[idx];
            __syncthreads();  // W visible

            const unsigned* sxp = sx + ((tig * 5 + dh) * IWT + wn) * PD + gid;
            const uint4* swp = sw4 + wm * MT * 32 + lane;

#pragma unroll
            for (int dw = 0; dw < 5; ++dw) {
#pragma unroll
                for (int dd = 0; dd < 5; ++dd) {
                    const int j = dw * 5 + dd;
                    uint4 a[MT];
#pragma unroll
                    for (int mt = 0; mt < MT; ++mt)
                        a[mt] = swp[(j * WM * MT + mt) * 32];
#pragma unroll
                    for (int nt = 0; nt < NT; ++nt) {
                        unsigned b0 = sxp[dw * PD + dd + nt * 8];
                        unsigned b1 = sxp[4 * CSTRIDE + dw * PD + dd + nt * 8];
#pragma unroll
                        for (int mt = 0; mt < MT; ++mt)
                            mma_tf32(acc[mt][nt], (const unsigned*)&a[mt], b0, b1);
                    }
                }
            }
        }
    }

    // ---------------- epilogue: bias (+gelu) (+accum) ----------------
    const int w_out = bw * WT + wn;
#pragma unroll
    for (int mt = 0; mt < MT; ++mt) {
        const int co0 = mb + mt * 16 + gid;
        const float bs0 = bias[co0], bs1 = bias[co0 + 8];
#pragma unroll
        for (int nt = 0; nt < NT; ++nt) {
            const int d = nt * 8 + 2 * tig;
            float v[4];
            v[0] = acc[mt][nt][0] + bs0;
            v[1] = acc[mt][nt][1] + bs0;
            v[2] = acc[mt][nt][2] + bs1;
            v[3] = acc[mt][nt][3] + bs1;
            if (GELU) {
#pragma unroll
                for (int q = 0; q < 4; ++q)
                    v[q] = 0.5f * v[q] *
                           (1.f + erff(v[q] * 0.70710678118654752f));
            }
            float2* o0 = (float2*)(out +
                ((((size_t)b * COUT + co0) * 32 + h) * 32 + w_out) * 32 + d);
            float2* o1 = (float2*)(out +
                ((((size_t)b * COUT + co0 + 8) * 32 + h) * 32 + w_out) * 32 + d);
            if (ACCUM) {
                float2 e0 = *o0, e1 = *o1;
                v[0] += e0.x; v[1] += e0.y; v[2] += e1.x; v[3] += e1.y;
            }
            *o0 = make_float2(v[0], v[1]);
            *o1 = make_float2(v[2], v[3]);
        }
    }
}

// ------------------------------- launch ---------------------------------------
extern "C" void kernel_launch(void* const* d_in, const int* in_sizes, int n_in,
                              void* d_out, int out_size) {
    const float* x     = (const float*)d_in[0];
    const float* basis = (const float*)d_in[1];
    const float* mixer = (const float*)d_in[2];
    const float* wq    = (const float*)d_in[3];
    const float* wk    = (const float*)d_in[4];
    const float* wv    = (const float*)d_in[5];
    const float* c1w   = (const float*)d_in[6];
    const float* c1b   = (const float*)d_in[7];
    const float* c2w   = (const float*)d_in[8];
    const float* c2b   = (const float*)d_in[9];
    const float* alpha = (const float*)d_in[10];
    float* out = (float*)d_out;

    unsigned *wtp1, *wtp2;
    float *hbuf;
    cudaGetSymbolAddress((void**)&wtp1, g_wtp1);
    cudaGetSymbolAddress((void**)&wtp2, g_wtp2);
    cudaGetSymbolAddress((void**)&hbuf, g_h);

    // conv1: CIN=128, COUT=64, WT=4, WM=2: X 8*5*8*37 + Wfrag 25*2*2*128
    constexpr int SM1 = (8 * 5 * 8 * pick_pd(8) + 25 * 2 * 2 * 128) * 4;
    // conv2: CIN=64, COUT=32, WT=8, WM=1: X 8*5*12*38 + Wfrag 25*1*2*128
    constexpr int SM2 = (8 * 5 * 12 * pick_pd(12) + 25 * 1 * 2 * 128) * 4;

    cudaFuncSetAttribute((const void*)k_conv_tc<128, 64, 4, 2, true, false>,
                         cudaFuncAttributeMaxDynamicSharedMemorySize, SM1);
    cudaFuncSetAttribute((const void*)k_conv_tc<64, 32, 8, 1, false, true>,
                         cudaFuncAttributeMaxDynamicSharedMemorySize, SM2);

    k_wtp<128, 64, 2, 2><<<256, 256>>>(c1w, wtp1);
    k_wtp<64, 32, 1, 2><<<64, 256>>>(c2w, wtp2);
    k_pre<<<S / 256, 256>>>(basis, mixer, wq, wk, wv);
    k_attn<<<(BATCH * S) / 256, 256>>>(x, wv, alpha, out);
    k_conv_tc<128, 64, 4, 2, true, false>
        <<<dim3(8, 32, 4), 256, SM1>>>(x, wtp1, c1b, hbuf);
    k_conv_tc<64, 32, 8, 1, false, true>
        <<<dim3(4, 32, 4), 256, SM2>>>(hbuf, wtp2, c2b, out);
}

// round 8
// speedup vs baseline: 5.5695x; 1.8390x over previous
#include <cuda_runtime.h>
#include <cuda_fp16.h>
#include <math.h>

static constexpr int BATCH = 4;
static constexpr int MG = 4;           // aligned groups
static constexpr int C = 32;
static constexpr int S = 32 * 32 * 32; // spatial voxels
static constexpr float SCALE = 0.17677669529663687f; // 1/sqrt(32)

// ---------------- device scratch (no runtime allocation allowed) --------------
__device__ float g_u[4 * C * S];       // u_j[c,s] for j=0..3 (batch-independent)
__device__ float g_vt[C * S];          // Wv4 @ token
__device__ float g_l4[S];              // token-vs-token logit (batch-independent)
__device__ float g_h[BATCH * 64 * S];  // conv1+gelu intermediate
__device__ unsigned g_wtp1[128 * 125 * 64 / 2]; // conv1 W frag-permuted f16x2
__device__ unsigned g_wtp2[64 * 125 * 32 / 2];  // conv2 W frag-permuted f16x2

// ---------- weight permute: [co][cin][tap] -> [cc][dh][j][wm][mt][lane][q] ----
// Each 32-bit word packs an f16x2 (cin pair) in the exact per-thread
// m16n8k16 A-fragment order: q=0 row gid k=2tig, q=1 row gid+8 k=2tig,
// q=2 row gid k=2tig+8, q=3 row gid+8 k=2tig+8.
template <int CIN, int COUT, int WM, int MT>
__global__ void k_wtp(const float* __restrict__ w, unsigned* __restrict__ wtp) {
    int n = CIN * 125 * COUT / 2;
    for (int p = blockIdx.x * blockDim.x + threadIdx.x; p < n;
         p += gridDim.x * blockDim.x) {
        int q    = p & 3;
        int lane = (p >> 2) & 31;
        int r    = p >> 7;
        int mt = r % MT; r /= MT;
        int wm = r % WM; r /= WM;
        int j  = r % 25; r /= 25;
        int dh = r % 5;
        int cc = r / 5;
        int gid = lane >> 2, tig = lane & 3;
        int co   = wm * (MT * 16) + mt * 16 + gid + 8 * (q & 1);
        int cin0 = cc * 16 + 2 * tig + 8 * (q >> 1);
        int tap  = dh * 25 + j;
        float lo = w[((size_t)co * CIN + cin0) * 125 + tap];
        float hi = w[((size_t)co * CIN + cin0 + 1) * 125 + tap];
        __half2 hh = __floats2half2_rn(lo, hi);
        wtp[p] = *(unsigned*)&hh;
    }
}

// ---------------- K1: batch-independent attention precompute ------------------
__global__ void k_pre(const float* __restrict__ basis, const float* __restrict__ mixer,
                      const float* __restrict__ wq, const float* __restrict__ wk,
                      const float* __restrict__ wv) {
    __shared__ float smm[C * 8];
    __shared__ float smq[C * C];
    __shared__ float smk[5 * C * C];
    __shared__ float smv[C * C];
    int tid = threadIdx.x;
    for (int t = tid; t < C * 8; t += blockDim.x)     smm[t] = mixer[t];
    for (int t = tid; t < C * C; t += blockDim.x)     smq[t] = wq[4 * C * C + t];
    for (int t = tid; t < 5 * C * C; t += blockDim.x) smk[t] = wk[t];
    for (int t = tid; t < C * C; t += blockDim.x)     smv[t] = wv[4 * C * C + t];
    __syncthreads();

    int s = blockIdx.x * blockDim.x + tid;
    float br[8];
#pragma unroll
    for (int r = 0; r < 8; ++r) br[r] = basis[r * S + s];

    float tok[C];
#pragma unroll
    for (int c = 0; c < C; ++c) {
        float a = 0.f;
#pragma unroll
        for (int r = 0; r < 8; ++r) a += smm[c * 8 + r] * br[r];
        tok[c] = a;
    }
    float q4[C];
#pragma unroll
    for (int o = 0; o < C; ++o) {
        float a = 0.f;
        for (int c = 0; c < C; ++c) a += smq[o * C + c] * tok[c];
        q4[o] = a;
    }
    for (int j = 0; j < 4; ++j) {
        for (int c = 0; c < C; ++c) {
            float a = 0.f;
            for (int o = 0; o < C; ++o) a += q4[o] * smk[(j * C + o) * C + c];
            g_u[(j * C + c) * S + s] = a;
        }
    }
    float l4 = 0.f;
    for (int c = 0; c < C; ++c) {
        float a = 0.f;
        for (int o = 0; o < C; ++o) a += q4[o] * smk[(4 * C + o) * C + c];
        l4 += a * tok[c];
    }
    g_l4[s] = l4 * SCALE;

    for (int c = 0; c < C; ++c) {
        float a = 0.f;
        for (int cp = 0; cp < C; ++cp) a += smv[c * C + cp] * tok[cp];
        g_vt[c * S + s] = a;
    }
}

// ---------------- K2: per-(b,s) attention combine -> out = alpha * att --------
__global__ void k_attn(const float* __restrict__ x, const float* __restrict__ wv,
                       const float* __restrict__ alpha, float* __restrict__ out) {
    __shared__ float smwv[4 * C * C]; // [j][cp][c]
    int tid = threadIdx.x;
    for (int t = tid; t < 4 * C * C; t += blockDim.x) {
        int c  = t % C;
        int cp = (t / C) % C;
        int j  = t / (C * C);
        smwv[t] = wv[(j * C + c) * C + cp];
    }
    __syncthreads();

    int idx = blockIdx.x * blockDim.x + tid;
    int b = idx >> 15;
    int s = idx & (S - 1);
    const float* xb = x + (size_t)b * MG * C * S + s;

    float l[5];
    for (int j = 0; j < 4; ++j) {
        float a = 0.f;
        for (int c = 0; c < C; ++c)
            a += g_u[(j * C + c) * S + s] * xb[(j * C + c) * S];
        l[j] = a * SCALE;
    }
    l[4] = g_l4[s];

    float m = l[0];
#pragma unroll
    for (int j = 1; j < 5; ++j) m = fmaxf(m, l[j]);
    float p[5], sum = 0.f;
#pragma unroll
    for (int j = 0; j < 5; ++j) { p[j] = expf(l[j] - m); sum += p[j]; }
    float inv = 1.f / sum;
#pragma unroll
    for (int j = 0; j < 5; ++j) p[j] *= inv;

    float o_[C];
#pragma unroll
    for (int c = 0; c < C; ++c) o_[c] = p[4] * g_vt[c * S + s];
    for (int j = 0; j < 4; ++j) {
        for (int cp = 0; cp < C; ++cp) {
            float xv = p[j] * xb[(j * C + cp) * S];
            const float* wp = &smwv[(j * C + cp) * C];
#pragma unroll
            for (int c = 0; c < C; ++c) o_[c] += wp[c] * xv;
        }
    }
    float a0 = alpha[0];
#pragma unroll
    for (int c = 0; c < C; ++c)
        out[((size_t)b * C + c) * S + s] = a0 * o_[c];
}

// ======================= fp16 tensor-core conv ================================
// Implicit GEMM with m16n8k16 fp16 mma (f32 accumulate). cin chunks of 16
// (one K per mma). X staged as f16x2 cin-pairs: word layout [kp8][ih5][IWT][PD].
// B reg0 = kpair tig, reg1 = kpair tig+4 (addressing identical to the tf32
// version with ci -> kpair).

__device__ __forceinline__ void mma_f16(float* c, const unsigned* a,
                                        unsigned b0, unsigned b1) {
    asm volatile(
        "mma.sync.aligned.m16n8k16.row.col.f32.f16.f16.f32 "
        "{%0,%1,%2,%3}, {%4,%5,%6,%7}, {%8,%9}, {%0,%1,%2,%3};"
        : "+f"(c[0]), "+f"(c[1]), "+f"(c[2]), "+f"(c[3])
        : "r"(a[0]), "r"(a[1]), "r"(a[2]), "r"(a[3]), "r"(b0), "r"(b1));
}

// pick d-dim padding so the kpair-stride of the X tile is ≡ 8 (mod 32) -> the
// 32 lanes of a B-fragment load hit 32 distinct banks.
__host__ __device__ constexpr int pick_pd(int iwt) {
    for (int p = 37; p < 64; ++p)
        if ((5 * iwt * p) % 32 == 8) return p;
    return 37;
}

template <int CIN, int COUT, int WT, int WM, bool GELU, bool ACCUM>
__global__ __launch_bounds__(256, 2)
void k_conv_tc(const float* __restrict__ in, const unsigned* __restrict__ wtp,
               const float* __restrict__ bias, float* __restrict__ out) {
    constexpr int WN  = 8 / WM;           // warps along n (= w positions/block)
    static_assert(WN == WT, "one w per n-warp");
    constexpr int MT  = COUT / (16 * WM); // m16-tiles per warp
    constexpr int NT  = 4;                // n8-tiles per warp (n = 32 d)
    constexpr int IWT = WT + 4;           // w halo
    constexpr int PD  = pick_pd(IWT);     // padded d dim (36 valid + pad)
    constexpr int XN  = 8 * 5 * IWT * PD; // X tile words (8 kpairs x 5 ih)
    constexpr int WEL = 25 * WM * MT * 128; // W frag words per (cin16-chunk, dh)
    constexpr int KSTRIDE = 5 * IWT * PD; // kpair stride in X tile (words)

    extern __shared__ unsigned smem_u[];
    unsigned* sx = smem_u;                 // [8][5][IWT][PD] f16x2 words
    uint4*    sw4 = (uint4*)(smem_u + XN); // [25][WM][MT][32] uint4 fragments

    const int bw  = blockIdx.x;
    const int h   = blockIdx.y;
    const int b   = blockIdx.z;
    const int tid = threadIdx.x;
    const int lane = tid & 31, wid = tid >> 5;
    const int gid  = lane >> 2, tig = lane & 3;
    const int wm = wid % WM, wn = wid / WM;
    const int mb = wm * (MT * 16);

    float acc[MT][NT][4];
#pragma unroll
    for (int mt = 0; mt < MT; ++mt)
#pragma unroll
        for (int nt = 0; nt < NT; ++nt)
#pragma unroll
            for (int q = 0; q < 4; ++q) acc[mt][nt][q] = 0.f;

    const float* inb = in + (size_t)b * CIN * S;

    for (int cc = 0; cc < CIN / 16; ++cc) {
        __syncthreads();  // everyone done with previous X (and W)
        // ---- stage X tile: 16 cin as 8 f16x2 pairs, 5 ih rows, halo w,d ----
        for (int idx = tid; idx < XN; idx += 256) {
            int ids = idx % PD;
            int r   = idx / PD;
            int iws = r % IWT; r /= IWT;
            int ihs = r % 5;
            int kp  = r / 5;
            int id = ids - 2, iw = bw * WT + iws - 2, ih = h + ihs - 2;
            float v0 = 0.f, v1 = 0.f;
            if ((unsigned)id < 32u && (unsigned)iw < 32u && (unsigned)ih < 32u) {
                const float* p =
                    inb + (size_t)(cc * 16 + 2 * kp) * S + ih * 1024 + iw * 32 + id;
                v0 = p[0];
                v1 = p[S];
            }
            __half2 hh = __floats2half2_rn(v0, v1);
            sx[idx] = *(unsigned*)&hh;
        }
        for (int dh = 0; dh < 5; ++dh) {
            __syncthreads();  // X visible / previous W use finished
            // ---- stage W fragments: contiguous coalesced uint4 copy ----
            const uint4* wsrc = (const uint4*)(wtp + (size_t)(cc * 5 + dh) * WEL);
#pragma unroll
            for (int idx = tid; idx < WEL / 4; idx += 256)
                sw4[idx] = wsrc[idx];
            __syncthreads();  // W visible

            const unsigned* sxp = sx + ((tig * 5 + dh) * IWT + wn) * PD + gid;
            const uint4* swp = sw4 + wm * MT * 32 + lane;

#pragma unroll
            for (int dw = 0; dw < 5; ++dw) {
#pragma unroll
                for (int dd = 0; dd < 5; ++dd) {
                    const int j = dw * 5 + dd;
                    uint4 a[MT];
#pragma unroll
                    for (int mt = 0; mt < MT; ++mt)
                        a[mt] = swp[(j * WM * MT + mt) * 32];
#pragma unroll
                    for (int nt = 0; nt < NT; ++nt) {
                        unsigned b0 = sxp[dw * PD + dd + nt * 8];
                        unsigned b1 = sxp[4 * KSTRIDE + dw * PD + dd + nt * 8];
#pragma unroll
                        for (int mt = 0; mt < MT; ++mt)
                            mma_f16(acc[mt][nt], (const unsigned*)&a[mt], b0, b1);
                    }
                }
            }
        }
    }

    // ---------------- epilogue: bias (+gelu) (+accum) ----------------
    const int w_out = bw * WT + wn;
#pragma unroll
    for (int mt = 0; mt < MT; ++mt) {
        const int co0 = mb + mt * 16 + gid;
        const float bs0 = bias[co0], bs1 = bias[co0 + 8];
#pragma unroll
        for (int nt = 0; nt < NT; ++nt) {
            const int d = nt * 8 + 2 * tig;
            float v[4];
            v[0] = acc[mt][nt][0] + bs0;
            v[1] = acc[mt][nt][1] + bs0;
            v[2] = acc[mt][nt][2] + bs1;
            v[3] = acc[mt][nt][3] + bs1;
            if (GELU) {
#pragma unroll
                for (int q = 0; q < 4; ++q)
                    v[q] = 0.5f * v[q] *
                           (1.f + erff(v[q] * 0.70710678118654752f));
            }
            float2* o0 = (float2*)(out +
                ((((size_t)b * COUT + co0) * 32 + h) * 32 + w_out) * 32 + d);
            float2* o1 = (float2*)(out +
                ((((size_t)b * COUT + co0 + 8) * 32 + h) * 32 + w_out) * 32 + d);
            if (ACCUM) {
                float2 e0 = *o0, e1 = *o1;
                v[0] += e0.x; v[1] += e0.y; v[2] += e1.x; v[3] += e1.y;
            }
            *o0 = make_float2(v[0], v[1]);
            *o1 = make_float2(v[2], v[3]);
        }
    }
}

// ------------------------------- launch ---------------------------------------
extern "C" void kernel_launch(void* const* d_in, const int* in_sizes, int n_in,
                              void* d_out, int out_size) {
    const float* x     = (const float*)d_in[0];
    const float* basis = (const float*)d_in[1];
    const float* mixer = (const float*)d_in[2];
    const float* wq    = (const float*)d_in[3];
    const float* wk    = (const float*)d_in[4];
    const float* wv    = (const float*)d_in[5];
    const float* c1w   = (const float*)d_in[6];
    const float* c1b   = (const float*)d_in[7];
    const float* c2w   = (const float*)d_in[8];
    const float* c2b   = (const float*)d_in[9];
    const float* alpha = (const float*)d_in[10];
    float* out = (float*)d_out;

    unsigned *wtp1, *wtp2;
    float *hbuf;
    cudaGetSymbolAddress((void**)&wtp1, g_wtp1);
    cudaGetSymbolAddress((void**)&wtp2, g_wtp2);
    cudaGetSymbolAddress((void**)&hbuf, g_h);

    // conv1: CIN=128, COUT=64, WT=4, WM=2: X 8*5*8*37 + Wfrag 25*2*2*128
    constexpr int SM1 = (8 * 5 * 8 * pick_pd(8) + 25 * 2 * 2 * 128) * 4;
    // conv2: CIN=64, COUT=32, WT=8, WM=1: X 8*5*12*38 + Wfrag 25*1*2*128
    constexpr int SM2 = (8 * 5 * 12 * pick_pd(12) + 25 * 1 * 2 * 128) * 4;

    cudaFuncSetAttribute((const void*)k_conv_tc<128, 64, 4, 2, true, false>,
                         cudaFuncAttributeMaxDynamicSharedMemorySize, SM1);
    cudaFuncSetAttribute((const void*)k_conv_tc<64, 32, 8, 1, false, true>,
                         cudaFuncAttributeMaxDynamicSharedMemorySize, SM2);

    k_wtp<128, 64, 2, 2><<<256, 256>>>(c1w, wtp1);
    k_wtp<64, 32, 1, 2><<<64, 256>>>(c2w, wtp2);
    k_pre<<<S / 256, 256>>>(basis, mixer, wq, wk, wv);
    k_attn<<<(BATCH * S) / 256, 256>>>(x, wv, alpha, out);
    k_conv_tc<128, 64, 4, 2, true, false>
        <<<dim3(8, 32, 4), 256, SM1>>>(x, wtp1, c1b, hbuf);
    k_conv_tc<64, 32, 8, 1, false, true>
        <<<dim3(4, 32, 4), 256, SM2>>>(hbuf, wtp2, c2b, out);
}

// round 9
// speedup vs baseline: 5.8019x; 1.0417x over previous
#include <cuda_runtime.h>
#include <cuda_fp16.h>
#include <math.h>

static constexpr int BATCH = 4;
static constexpr int MG = 4;           // aligned groups
static constexpr int C = 32;
static constexpr int S = 32 * 32 * 32; // spatial voxels
static constexpr float SCALE = 0.17677669529663687f; // 1/sqrt(32)

// ---------------- device scratch (no runtime allocation allowed) --------------
__device__ float g_u[4 * C * S];       // u_j[c,s] for j=0..3 (batch-independent)
__device__ float g_vt[C * S];          // Wv4 @ token
__device__ float g_l4[S];              // token-vs-token logit (batch-independent)
__device__ float g_h[BATCH * 64 * S];  // conv1+gelu intermediate
__device__ unsigned g_wtp1[128 * 125 * 64 / 2]; // conv1 W frag-permuted f16x2
__device__ unsigned g_wtp2[64 * 125 * 32 / 2];  // conv2 W frag-permuted f16x2

// ---------- weight permute: [co][cin][tap] -> [cc][dh][j][wm][mt][lane][q] ----
// Each 32-bit word packs an f16x2 (cin pair) in the exact per-thread
// m16n8k16 A-fragment order: q=0 row gid k=2tig, q=1 row gid+8 k=2tig,
// q=2 row gid k=2tig+8, q=3 row gid+8 k=2tig+8.
template <int CIN, int COUT, int WM, int MT>
__global__ void k_wtp(const float* __restrict__ w, unsigned* __restrict__ wtp) {
    int n = CIN * 125 * COUT / 2;
    for (int p = blockIdx.x * blockDim.x + threadIdx.x; p < n;
         p += gridDim.x * blockDim.x) {
        int q    = p & 3;
        int lane = (p >> 2) & 31;
        int r    = p >> 7;
        int mt = r % MT; r /= MT;
        int wm = r % WM; r /= WM;
        int j  = r % 25; r /= 25;
        int dh = r % 5;
        int cc = r / 5;
        int gid = lane >> 2, tig = lane & 3;
        int co   = wm * (MT * 16) + mt * 16 + gid + 8 * (q & 1);
        int cin0 = cc * 16 + 2 * tig + 8 * (q >> 1);
        int tap  = dh * 25 + j;
        float lo = w[((size_t)co * CIN + cin0) * 125 + tap];
        float hi = w[((size_t)co * CIN + cin0 + 1) * 125 + tap];
        __half2 hh = __floats2half2_rn(lo, hi);
        wtp[p] = *(unsigned*)&hh;
    }
}

// ---------------- K1: batch-independent attention precompute ------------------
__global__ void k_pre(const float* __restrict__ basis, const float* __restrict__ mixer,
                      const float* __restrict__ wq, const float* __restrict__ wk,
                      const float* __restrict__ wv) {
    __shared__ float smm[C * 8];
    __shared__ float smq[C * C];
    __shared__ float smk[5 * C * C];
    __shared__ float smv[C * C];
    int tid = threadIdx.x;
    for (int t = tid; t < C * 8; t += blockDim.x)     smm[t] = mixer[t];
    for (int t = tid; t < C * C; t += blockDim.x)     smq[t] = wq[4 * C * C + t];
    for (int t = tid; t < 5 * C * C; t += blockDim.x) smk[t] = wk[t];
    for (int t = tid; t < C * C; t += blockDim.x)     smv[t] = wv[4 * C * C + t];
    __syncthreads();

    int s = blockIdx.x * blockDim.x + tid;
    float br[8];
#pragma unroll
    for (int r = 0; r < 8; ++r) br[r] = basis[r * S + s];

    float tok[C];
#pragma unroll
    for (int c = 0; c < C; ++c) {
        float a = 0.f;
#pragma unroll
        for (int r = 0; r < 8; ++r) a += smm[c * 8 + r] * br[r];
        tok[c] = a;
    }
    float q4[C];
#pragma unroll
    for (int o = 0; o < C; ++o) {
        float a = 0.f;
        for (int c = 0; c < C; ++c) a += smq[o * C + c] * tok[c];
        q4[o] = a;
    }
    for (int j = 0; j < 4; ++j) {
        for (int c = 0; c < C; ++c) {
            float a = 0.f;
            for (int o = 0; o < C; ++o) a += q4[o] * smk[(j * C + o) * C + c];
            g_u[(j * C + c) * S + s] = a;
        }
    }
    float l4 = 0.f;
    for (int c = 0; c < C; ++c) {
        float a = 0.f;
        for (int o = 0; o < C; ++o) a += q4[o] * smk[(4 * C + o) * C + c];
        l4 += a * tok[c];
    }
    g_l4[s] = l4 * SCALE;

    for (int c = 0; c < C; ++c) {
        float a = 0.f;
        for (int cp = 0; cp < C; ++cp) a += smv[c * C + cp] * tok[cp];
        g_vt[c * S + s] = a;
    }
}

// ---------------- K2: per-(b,s) attention combine -> out = alpha * att --------
__global__ void k_attn(const float* __restrict__ x, const float* __restrict__ wv,
                       const float* __restrict__ alpha, float* __restrict__ out) {
    __shared__ float smwv[4 * C * C]; // [j][cp][c]
    int tid = threadIdx.x;
    for (int t = tid; t < 4 * C * C; t += blockDim.x) {
        int c  = t % C;
        int cp = (t / C) % C;
        int j  = t / (C * C);
        smwv[t] = wv[(j * C + c) * C + cp];
    }
    __syncthreads();

    int idx = blockIdx.x * blockDim.x + tid;
    int b = idx >> 15;
    int s = idx & (S - 1);
    const float* xb = x + (size_t)b * MG * C * S + s;

    float l[5];
    for (int j = 0; j < 4; ++j) {
        float a = 0.f;
        for (int c = 0; c < C; ++c)
            a += g_u[(j * C + c) * S + s] * xb[(j * C + c) * S];
        l[j] = a * SCALE;
    }
    l[4] = g_l4[s];

    float m = l[0];
#pragma unroll
    for (int j = 1; j < 5; ++j) m = fmaxf(m, l[j]);
    float p[5], sum = 0.f;
#pragma unroll
    for (int j = 0; j < 5; ++j) { p[j] = expf(l[j] - m); sum += p[j]; }
    float inv = 1.f / sum;
#pragma unroll
    for (int j = 0; j < 5; ++j) p[j] *= inv;

    float o_[C];
#pragma unroll
    for (int c = 0; c < C; ++c) o_[c] = p[4] * g_vt[c * S + s];
    for (int j = 0; j < 4; ++j) {
        for (int cp = 0; cp < C; ++cp) {
            float xv = p[j] * xb[(j * C + cp) * S];
            const float* wp = &smwv[(j * C + cp) * C];
#pragma unroll
            for (int c = 0; c < C; ++c) o_[c] += wp[c] * xv;
        }
    }
    float a0 = alpha[0];
#pragma unroll
    for (int c = 0; c < C; ++c)
        out[((size_t)b * C + c) * S + s] = a0 * o_[c];
}

// ======================= fp16 tensor-core conv ================================
// Implicit GEMM with m16n8k16 fp16 mma (f32 accumulate). cin chunks of 16
// (one K per mma). X staged as f16x2 cin-pairs: word layout [kp8][ih5][IWT][PD].

__device__ __forceinline__ void mma_f16(float* c, const unsigned* a,
                                        unsigned b0, unsigned b1) {
    asm volatile(
        "mma.sync.aligned.m16n8k16.row.col.f32.f16.f16.f32 "
        "{%0,%1,%2,%3}, {%4,%5,%6,%7}, {%8,%9}, {%0,%1,%2,%3};"
        : "+f"(c[0]), "+f"(c[1]), "+f"(c[2]), "+f"(c[3])
        : "r"(a[0]), "r"(a[1]), "r"(a[2]), "r"(a[3]), "r"(b0), "r"(b1));
}

// pick d-dim padding so the kpair-stride of the X tile is ≡ 8 (mod 32) -> the
// 32 lanes of a B-fragment load hit 32 distinct banks.
__host__ __device__ constexpr int pick_pd(int iwt) {
    for (int p = 37; p < 64; ++p)
        if ((5 * iwt * p) % 32 == 8) return p;
    return 37;
}

template <int CIN, int COUT, int WT, int WM, bool GELU, bool ACCUM>
__global__ __launch_bounds__(256, 2)
void k_conv_tc(const float* __restrict__ in, const unsigned* __restrict__ wtp,
               const float* __restrict__ bias, float* __restrict__ out) {
    constexpr int WN  = 8 / WM;           // warps along n (= w positions/block)
    static_assert(WN == WT, "one w per n-warp");
    constexpr int MT  = COUT / (16 * WM); // m16-tiles per warp
    constexpr int NT  = 4;                // n8-tiles per warp (n = 32 d)
    constexpr int IWT = WT + 4;           // w halo
    constexpr int PD  = pick_pd(IWT);     // padded d dim (36 valid + pad)
    constexpr int XN  = 8 * 5 * IWT * PD; // X tile words (8 kpairs x 5 ih)
    constexpr int WEL = 25 * WM * MT * 128; // W frag words per (cin16-chunk, dh)
    constexpr int KSTRIDE = 5 * IWT * PD; // kpair stride in X tile (words)

    extern __shared__ unsigned smem_u[];
    unsigned* sx = smem_u;                 // [8][5][IWT][PD] f16x2 words
    uint4*    sw4 = (uint4*)(smem_u + XN); // [25][WM][MT][32] uint4 fragments

    const int bw  = blockIdx.x;
    const int h   = blockIdx.y;
    const int b   = blockIdx.z;
    const int tid = threadIdx.x;
    const int lane = tid & 31, wid = tid >> 5;
    const int gid  = lane >> 2, tig = lane & 3;
    const int wm = wid % WM, wn = wid / WM;
    const int mb = wm * (MT * 16);

    float acc[MT][NT][4];
#pragma unroll
    for (int mt = 0; mt < MT; ++mt)
#pragma unroll
        for (int nt = 0; nt < NT; ++nt)
#pragma unroll
            for (int q = 0; q < 4; ++q) acc[mt][nt][q] = 0.f;

    const float* inb = in + (size_t)b * CIN * S;

    for (int cc = 0; cc < CIN / 16; ++cc) {
        __syncthreads();  // everyone done with previous X (and W)
        // ---- stage X tile: 16 cin as 8 f16x2 pairs, 5 ih rows, halo w,d ----
        for (int idx = tid; idx < XN; idx += 256) {
            int ids = idx % PD;
            int r   = idx / PD;
            int iws = r % IWT; r /= IWT;
            int ihs = r % 5;
            int kp  = r / 5;
            int id = ids - 2, iw = bw * WT + iws - 2, ih = h + ihs - 2;
            float v0 = 0.f, v1 = 0.f;
            if ((unsigned)id < 32u && (unsigned)iw < 32u && (unsigned)ih < 32u) {
                const float* p =
                    inb + (size_t)(cc * 16 + 2 * kp) * S + ih * 1024 + iw * 32 + id;
                v0 = p[0];
                v1 = p[S];
            }
            __half2 hh = __floats2half2_rn(v0, v1);
            sx[idx] = *(unsigned*)&hh;
        }
        for (int dh = 0; dh < 5; ++dh) {
            __syncthreads();  // X visible / previous W use finished
            // ---- stage W fragments: contiguous coalesced uint4 copy ----
            const uint4* wsrc = (const uint4*)(wtp + (size_t)(cc * 5 + dh) * WEL);
#pragma unroll
            for (int idx = tid; idx < WEL / 4; idx += 256)
                sw4[idx] = wsrc[idx];
            __syncthreads();  // W visible

            const unsigned* sxp = sx + ((tig * 5 + dh) * IWT + wn) * PD + gid;
            const uint4* swp = sw4 + wm * MT * 32 + lane;

#pragma unroll
            for (int dw = 0; dw < 5; ++dw) {
#pragma unroll
                for (int dd = 0; dd < 5; ++dd) {
                    const int j = dw * 5 + dd;
                    uint4 a[MT];
#pragma unroll
                    for (int mt = 0; mt < MT; ++mt)
                        a[mt] = swp[(j * WM * MT + mt) * 32];
#pragma unroll
                    for (int nt = 0; nt < NT; ++nt) {
                        unsigned b0 = sxp[dw * PD + dd + nt * 8];
                        unsigned b1 = sxp[4 * KSTRIDE + dw * PD + dd + nt * 8];
#pragma unroll
                        for (int mt = 0; mt < MT; ++mt)
                            mma_f16(acc[mt][nt], (const unsigned*)&a[mt], b0, b1);
                    }
                }
            }
        }
    }

    // ---------------- epilogue: bias (+gelu) (+accum) ----------------
    const int w_out = bw * WT + wn;
#pragma unroll
    for (int mt = 0; mt < MT; ++mt) {
        const int co0 = mb + mt * 16 + gid;
        const float bs0 = bias[co0], bs1 = bias[co0 + 8];
#pragma unroll
        for (int nt = 0; nt < NT; ++nt) {
            const int d = nt * 8 + 2 * tig;
            float v[4];
            v[0] = acc[mt][nt][0] + bs0;
            v[1] = acc[mt][nt][1] + bs0;
            v[2] = acc[mt][nt][2] + bs1;
            v[3] = acc[mt][nt][3] + bs1;
            if (GELU) {
#pragma unroll
                for (int q = 0; q < 4; ++q)
                    v[q] = 0.5f * v[q] *
                           (1.f + erff(v[q] * 0.70710678118654752f));
            }
            float2* o0 = (float2*)(out +
                ((((size_t)b * COUT + co0) * 32 + h) * 32 + w_out) * 32 + d);
            float2* o1 = (float2*)(out +
                ((((size_t)b * COUT + co0 + 8) * 32 + h) * 32 + w_out) * 32 + d);
            if (ACCUM) {
                float2 e0 = *o0, e1 = *o1;
                v[0] += e0.x; v[1] += e0.y; v[2] += e1.x; v[3] += e1.y;
            }
            *o0 = make_float2(v[0], v[1]);
            *o1 = make_float2(v[2], v[3]);
        }
    }
}

// ------------------------------- launch ---------------------------------------
extern "C" void kernel_launch(void* const* d_in, const int* in_sizes, int n_in,
                              void* d_out, int out_size) {
    const float* x     = (const float*)d_in[0];
    const float* basis = (const float*)d_in[1];
    const float* mixer = (const float*)d_in[2];
    const float* wq    = (const float*)d_in[3];
    const float* wk    = (const float*)d_in[4];
    const float* wv    = (const float*)d_in[5];
    const float* c1w   = (const float*)d_in[6];
    const float* c1b   = (const float*)d_in[7];
    const float* c2w   = (const float*)d_in[8];
    const float* c2b   = (const float*)d_in[9];
    const float* alpha = (const float*)d_in[10];
    float* out = (float*)d_out;

    unsigned *wtp1, *wtp2;
    float *hbuf;
    cudaGetSymbolAddress((void**)&wtp1, g_wtp1);
    cudaGetSymbolAddress((void**)&wtp2, g_wtp2);
    cudaGetSymbolAddress((void**)&hbuf, g_h);

    // conv1: CIN=128, COUT=64, WT=4, WM=2: X 8*5*8*37 + Wfrag 25*2*2*128
    constexpr int SM1 = (8 * 5 * 8 * pick_pd(8) + 25 * 2 * 2 * 128) * 4;
    // conv2: CIN=64, COUT=32, WT=8, WM=1: X 8*5*12*38 + Wfrag 25*1*2*128
    constexpr int SM2 = (8 * 5 * 12 * pick_pd(12) + 25 * 1 * 2 * 128) * 4;

    cudaFuncSetAttribute((const void*)k_conv_tc<128, 64, 4, 2, true, false>,
                         cudaFuncAttributeMaxDynamicSharedMemorySize, SM1);
    cudaFuncSetAttribute((const void*)k_conv_tc<64, 32, 8, 1, false, true>,
                         cudaFuncAttributeMaxDynamicSharedMemorySize, SM2);

    // One-time host-side resources (created on the first, non-captured call).
    // Fork-join: side stream runs the fma/memory-bound attention path
    // concurrently with tensor-bound conv1.
    static cudaStream_t s_side = nullptr;
    static cudaEvent_t e_fork = nullptr, e_join = nullptr;
    if (s_side == nullptr) {
        cudaStreamCreateWithFlags(&s_side, cudaStreamNonBlocking);
        cudaEventCreateWithFlags(&e_fork, cudaEventDisableTiming);
        cudaEventCreateWithFlags(&e_join, cudaEventDisableTiming);
    }

    // fork
    cudaEventRecord(e_fork, (cudaStream_t)0);
    cudaStreamWaitEvent(s_side, e_fork, 0);

    // side: attention path + conv2 weight permute
    k_wtp<64, 32, 1, 2><<<64, 256, 0, s_side>>>(c2w, wtp2);
    k_pre<<<S / 256, 256, 0, s_side>>>(basis, mixer, wq, wk, wv);
    k_attn<<<(BATCH * S) / 256, 256, 0, s_side>>>(x, wv, alpha, out);
    cudaEventRecord(e_join, s_side);

    // main: conv1 path
    k_wtp<128, 64, 2, 2><<<256, 256>>>(c1w, wtp1);
    k_conv_tc<128, 64, 4, 2, true, false>
        <<<dim3(8, 32, 4), 256, SM1>>>(x, wtp1, c1b, hbuf);

    // join, then conv2 (needs conv1 output, wtp2, and attn-written out)
    cudaStreamWaitEvent((cudaStream_t)0, e_join, 0);
    k_conv_tc<64, 32, 8, 1, false, true>
        <<<dim3(4, 32, 4), 256, SM2>>>(hbuf, wtp2, c2b, out);
}

// round 11
// speedup vs baseline: 5.8620x; 1.0104x over previous
#include <cuda_runtime.h>
#include <cuda_fp16.h>
#include <math.h>

static constexpr int BATCH = 4;
static constexpr int MG = 4;           // aligned groups
static constexpr int C = 32;
static constexpr int S = 32 * 32 * 32; // spatial voxels
static constexpr float SCALE = 0.17677669529663687f; // 1/sqrt(32)

// ---------------- device scratch (no runtime allocation allowed) --------------
__device__ float g_u[4 * C * S];       // u_j[c,s] for j=0..3 (batch-independent)
__device__ float g_vt[C * S];          // Wv4 @ token
__device__ float g_l4[S];              // token-vs-token logit (batch-independent)
__device__ float g_h[BATCH * 64 * S];  // conv1+gelu intermediate
__device__ unsigned g_wtp1[128 * 125 * 64 / 2]; // conv1 W frag-permuted f16x2
__device__ unsigned g_wtp2[64 * 125 * 32 / 2];  // conv2 W frag-permuted f16x2

// ---------- weight permute: [co][cin][tap] -> [cc][dh][j][wm][mt][lane][q] ----
// Each 32-bit word packs an f16x2 (cin pair) in the exact per-thread
// m16n8k16 A-fragment order.
template <int CIN, int COUT, int WM, int MT>
__global__ void k_wtp(const float* __restrict__ w, unsigned* __restrict__ wtp) {
    int n = CIN * 125 * COUT / 2;
    for (int p = blockIdx.x * blockDim.x + threadIdx.x; p < n;
         p += gridDim.x * blockDim.x) {
        int q    = p & 3;
        int lane = (p >> 2) & 31;
        int r    = p >> 7;
        int mt = r % MT; r /= MT;
        int wm = r % WM; r /= WM;
        int j  = r % 25; r /= 25;
        int dh = r % 5;
        int cc = r / 5;
        int gid = lane >> 2, tig = lane & 3;
        int co   = wm * (MT * 16) + mt * 16 + gid + 8 * (q & 1);
        int cin0 = cc * 16 + 2 * tig + 8 * (q >> 1);
        int tap  = dh * 25 + j;
        float lo = w[((size_t)co * CIN + cin0) * 125 + tap];
        float hi = w[((size_t)co * CIN + cin0 + 1) * 125 + tap];
        __half2 hh = __floats2half2_rn(lo, hi);
        wtp[p] = *(unsigned*)&hh;
    }
}

// ---------------- K1: batch-independent attention precompute ------------------
__global__ void k_pre(const float* __restrict__ basis, const float* __restrict__ mixer,
                      const float* __restrict__ wq, const float* __restrict__ wk,
                      const float* __restrict__ wv) {
    __shared__ float smm[C * 8];
    __shared__ float smq[C * C];
    __shared__ float smk[5 * C * C];
    __shared__ float smv[C * C];
    int tid = threadIdx.x;
    for (int t = tid; t < C * 8; t += blockDim.x)     smm[t] = mixer[t];
    for (int t = tid; t < C * C; t += blockDim.x)     smq[t] = wq[4 * C * C + t];
    for (int t = tid; t < 5 * C * C; t += blockDim.x) smk[t] = wk[t];
    for (int t = tid; t < C * C; t += blockDim.x)     smv[t] = wv[4 * C * C + t];
    __syncthreads();

    int s = blockIdx.x * blockDim.x + tid;
    float br[8];
#pragma unroll
    for (int r = 0; r < 8; ++r) br[r] = basis[r * S + s];

    float tok[C];
#pragma unroll
    for (int c = 0; c < C; ++c) {
        float a = 0.f;
#pragma unroll
        for (int r = 0; r < 8; ++r) a += smm[c * 8 + r] * br[r];
        tok[c] = a;
    }
    float q4[C];
#pragma unroll
    for (int o = 0; o < C; ++o) {
        float a = 0.f;
        for (int c = 0; c < C; ++c) a += smq[o * C + c] * tok[c];
        q4[o] = a;
    }
    for (int j = 0; j < 4; ++j) {
        for (int c = 0; c < C; ++c) {
            float a = 0.f;
            for (int o = 0; o < C; ++o) a += q4[o] * smk[(j * C + o) * C + c];
            g_u[(j * C + c) * S + s] = a;
        }
    }
    float l4 = 0.f;
    for (int c = 0; c < C; ++c) {
        float a = 0.f;
        for (int o = 0; o < C; ++o) a += q4[o] * smk[(4 * C + o) * C + c];
        l4 += a * tok[c];
    }
    g_l4[s] = l4 * SCALE;

    for (int c = 0; c < C; ++c) {
        float a = 0.f;
        for (int cp = 0; cp < C; ++cp) a += smv[c * C + cp] * tok[cp];
        g_vt[c * S + s] = a;
    }
}

// ---------------- K2: per-(b,s) attention combine -> out = alpha * att --------
__global__ void k_attn(const float* __restrict__ x, const float* __restrict__ wv,
                       const float* __restrict__ alpha, float* __restrict__ out) {
    __shared__ float smwv[4 * C * C]; // [j][cp][c]
    int tid = threadIdx.x;
    for (int t = tid; t < 4 * C * C; t += blockDim.x) {
        int c  = t % C;
        int cp = (t / C) % C;
        int j  = t / (C * C);
        smwv[t] = wv[(j * C + c) * C + cp];
    }
    __syncthreads();

    int idx = blockIdx.x * blockDim.x + tid;
    int b = idx >> 15;
    int s = idx & (S - 1);
    const float* xb = x + (size_t)b * MG * C * S + s;

    float l[5];
    for (int j = 0; j < 4; ++j) {
        float a = 0.f;
        for (int c = 0; c < C; ++c)
            a += g_u[(j * C + c) * S + s] * xb[(j * C + c) * S];
        l[j] = a * SCALE;
    }
    l[4] = g_l4[s];

    float m = l[0];
#pragma unroll
    for (int j = 1; j < 5; ++j) m = fmaxf(m, l[j]);
    float p[5], sum = 0.f;
#pragma unroll
    for (int j = 0; j < 5; ++j) { p[j] = expf(l[j] - m); sum += p[j]; }
    float inv = 1.f / sum;
#pragma unroll
    for (int j = 0; j < 5; ++j) p[j] *= inv;

    float o_[C];
#pragma unroll
    for (int c = 0; c < C; ++c) o_[c] = p[4] * g_vt[c * S + s];
    for (int j = 0; j < 4; ++j) {
        for (int cp = 0; cp < C; ++cp) {
            float xv = p[j] * xb[(j * C + cp) * S];
            const float* wp = &smwv[(j * C + cp) * C];
#pragma unroll
            for (int c = 0; c < C; ++c) o_[c] += wp[c] * xv;
        }
    }
    float a0 = alpha[0];
#pragma unroll
    for (int c = 0; c < C; ++c)
        out[((size_t)b * C + c) * S + s] = a0 * o_[c];
}

// ======================= fp16 tensor-core conv ================================
// Implicit GEMM with m16n8k16 fp16 mma (f32 accumulate). cin chunks of 16
// (one K per mma). X staged as f16x2 cin-pairs: word layout [kp8][ih5][IWT][PD].

__device__ __forceinline__ void mma_f16(float* c, const unsigned* a,
                                        unsigned b0, unsigned b1) {
    asm volatile(
        "mma.sync.aligned.m16n8k16.row.col.f32.f16.f16.f32 "
        "{%0,%1,%2,%3}, {%4,%5,%6,%7}, {%8,%9}, {%0,%1,%2,%3};"
        : "+f"(c[0]), "+f"(c[1]), "+f"(c[2]), "+f"(c[3])
        : "r"(a[0]), "r"(a[1]), "r"(a[2]), "r"(a[3]), "r"(b0), "r"(b1));
}

// pick d-dim padding so the kpair-stride of the X tile is ≡ 8 (mod 32) -> the
// 32 lanes of a B-fragment load hit 32 distinct banks.
__host__ __device__ constexpr int pick_pd(int iwt) {
    for (int p = 37; p < 64; ++p)
        if ((5 * iwt * p) % 32 == 8) return p;
    return 37;
}

template <int CIN, int COUT, int WT, int WM, bool GELU, bool ACCUM>
__global__ __launch_bounds__(256, 2)
void k_conv_tc(const float* __restrict__ in, const unsigned* __restrict__ wtp,
               const float* __restrict__ bias, float* __restrict__ out,
               int h0) {
    constexpr int WN  = 8 / WM;           // warps along n (= w positions/block)
    static_assert(WN == WT, "one w per n-warp");
    constexpr int MT  = COUT / (16 * WM); // m16-tiles per warp
    constexpr int NT  = 4;                // n8-tiles per warp (n = 32 d)
    constexpr int IWT = WT + 4;           // w halo
    constexpr int PD  = pick_pd(IWT);     // padded d dim (36 valid + pad)
    constexpr int XN  = 8 * 5 * IWT * PD; // X tile words (8 kpairs x 5 ih)
    constexpr int WEL = 25 * WM * MT * 128; // W frag words per (cin16-chunk, dh)
    constexpr int KSTRIDE = 5 * IWT * PD; // kpair stride in X tile (words)

    extern __shared__ unsigned smem_u[];
    unsigned* sx = smem_u;                 // [8][5][IWT][PD] f16x2 words
    uint4*    sw4 = (uint4*)(smem_u + XN); // [25][WM][MT][32] uint4 fragments

    const int bw  = blockIdx.x;
    const int h   = blockIdx.y + h0;
    const int b   = blockIdx.z;
    const int tid = threadIdx.x;
    const int lane = tid & 31, wid = tid >> 5;
    const int gid  = lane >> 2, tig = lane & 3;
    const int wm = wid % WM, wn = wid / WM;
    const int mb = wm * (MT * 16);

    float acc[MT][NT][4];
#pragma unroll
    for (int mt = 0; mt < MT; ++mt)
#pragma unroll
        for (int nt = 0; nt < NT; ++nt)
#pragma unroll
            for (int q = 0; q < 4; ++q) acc[mt][nt][q] = 0.f;

    const float* inb = in + (size_t)b * CIN * S;

    for (int cc = 0; cc < CIN / 16; ++cc) {
        __syncthreads();  // everyone done with previous X (and W)
        // ---- stage X tile: 16 cin as 8 f16x2 pairs, 5 ih rows, halo w,d ----
        for (int idx = tid; idx < XN; idx += 256) {
            int ids = idx % PD;
            int r   = idx / PD;
            int iws = r % IWT; r /= IWT;
            int ihs = r % 5;
            int kp  = r / 5;
            int id = ids - 2, iw = bw * WT + iws - 2, ih = h + ihs - 2;
            float v0 = 0.f, v1 = 0.f;
            if ((unsigned)id < 32u && (unsigned)iw < 32u && (unsigned)ih < 32u) {
                const float* p =
                    inb + (size_t)(cc * 16 + 2 * kp) * S + ih * 1024 + iw * 32 + id;
                v0 = p[0];
                v1 = p[S];
            }
            __half2 hh = __floats2half2_rn(v0, v1);
            sx[idx] = *(unsigned*)&hh;
        }
        for (int dh = 0; dh < 5; ++dh) {
            __syncthreads();  // X visible / previous W use finished
            // ---- stage W fragments: contiguous coalesced uint4 copy ----
            const uint4* wsrc = (const uint4*)(wtp + (size_t)(cc * 5 + dh) * WEL);
#pragma unroll
            for (int idx = tid; idx < WEL / 4; idx += 256)
                sw4[idx] = wsrc[idx];
            __syncthreads();  // W visible

            const unsigned* sxp = sx + ((tig * 5 + dh) * IWT + wn) * PD + gid;
            const uint4* swp = sw4 + wm * MT * 32 + lane;

#pragma unroll
            for (int dw = 0; dw < 5; ++dw) {
#pragma unroll
                for (int dd = 0; dd < 5; ++dd) {
                    const int j = dw * 5 + dd;
                    uint4 a[MT];
#pragma unroll
                    for (int mt = 0; mt < MT; ++mt)
                        a[mt] = swp[(j * WM * MT + mt) * 32];
#pragma unroll
                    for (int nt = 0; nt < NT; ++nt) {
                        unsigned b0 = sxp[dw * PD + dd + nt * 8];
                        unsigned b1 = sxp[4 * KSTRIDE + dw * PD + dd + nt * 8];
#pragma unroll
                        for (int mt = 0; mt < MT; ++mt)
                            mma_f16(acc[mt][nt], (const unsigned*)&a[mt], b0, b1);
                    }
                }
            }
        }
    }

    // ---------------- epilogue: bias (+gelu) (+accum) ----------------
    const int w_out = bw * WT + wn;
#pragma unroll
    for (int mt = 0; mt < MT; ++mt) {
        const int co0 = mb + mt * 16 + gid;
        const float bs0 = bias[co0], bs1 = bias[co0 + 8];
#pragma unroll
        for (int nt = 0; nt < NT; ++nt) {
            const int d = nt * 8 + 2 * tig;
            float v[4];
            v[0] = acc[mt][nt][0] + bs0;
            v[1] = acc[mt][nt][1] + bs0;
            v[2] = acc[mt][nt][2] + bs1;
            v[3] = acc[mt][nt][3] + bs1;
            if (GELU) {
#pragma unroll
                for (int q = 0; q < 4; ++q)
                    v[q] = 0.5f * v[q] *
                           (1.f + erff(v[q] * 0.70710678118654752f));
            }
            float2* o0 = (float2*)(out +
                ((((size_t)b * COUT + co0) * 32 + h) * 32 + w_out) * 32 + d);
            float2* o1 = (float2*)(out +
                ((((size_t)b * COUT + co0 + 8) * 32 + h) * 32 + w_out) * 32 + d);
            if (ACCUM) {
                float2 e0 = *o0, e1 = *o1;
                v[0] += e0.x; v[1] += e0.y; v[2] += e1.x; v[3] += e1.y;
            }
            *o0 = make_float2(v[0], v[1]);
            *o1 = make_float2(v[2], v[3]);
        }
    }
}

// ------------------------------- launch ---------------------------------------
extern "C" void kernel_launch(void* const* d_in, const int* in_sizes, int n_in,
                              void* d_out, int out_size) {
    const float* x     = (const float*)d_in[0];
    const float* basis = (const float*)d_in[1];
    const float* mixer = (const float*)d_in[2];
    const float* wq    = (const float*)d_in[3];
    const float* wk    = (const float*)d_in[4];
    const float* wv    = (const float*)d_in[5];
    const float* c1w   = (const float*)d_in[6];
    const float* c1b   = (const float*)d_in[7];
    const float* c2w   = (const float*)d_in[8];
    const float* c2b   = (const float*)d_in[9];
    const float* alpha = (const float*)d_in[10];
    float* out = (float*)d_out;

    unsigned *wtp1, *wtp2;
    float *hbuf;
    cudaGetSymbolAddress((void**)&wtp1, g_wtp1);
    cudaGetSymbolAddress((void**)&wtp2, g_wtp2);
    cudaGetSymbolAddress((void**)&hbuf, g_h);

    constexpr int SM1 = (8 * 5 * 8 * pick_pd(8) + 25 * 2 * 2 * 128) * 4;
    constexpr int SM2 = (8 * 5 * 12 * pick_pd(12) + 25 * 1 * 2 * 128) * 4;

    cudaFuncSetAttribute((const void*)k_conv_tc<128, 64, 4, 2, true, false>,
                         cudaFuncAttributeMaxDynamicSharedMemorySize, SM1);
    cudaFuncSetAttribute((const void*)k_conv_tc<64, 32, 8, 1, false, true>,
                         cudaFuncAttributeMaxDynamicSharedMemorySize, SM2);

    // One-time host-side resources (created on first, non-captured call).
    static cudaStream_t s1 = nullptr, s2 = nullptr;
    static cudaEvent_t eF = nullptr, eA = nullptr, e1a = nullptr, e2a = nullptr;
    if (s1 == nullptr) {
        cudaStreamCreateWithFlags(&s1, cudaStreamNonBlocking);
        cudaStreamCreateWithFlags(&s2, cudaStreamNonBlocking);
        cudaEventCreateWithFlags(&eF, cudaEventDisableTiming);
        cudaEventCreateWithFlags(&eA, cudaEventDisableTiming);
        cudaEventCreateWithFlags(&e1a, cudaEventDisableTiming);
        cudaEventCreateWithFlags(&e2a, cudaEventDisableTiming);
    }

    // main: weight permutes (#1, #2)
    k_wtp<128, 64, 2, 2><<<256, 256>>>(c1w, wtp1);
    k_wtp<64, 32, 1, 2><<<64, 256>>>(c2w, wtp2);
    cudaEventRecord(eF, (cudaStream_t)0);

    // side s1: attention path (overlaps conv1)  (#3, #5)
    cudaStreamWaitEvent(s1, eF, 0);
    k_pre<<<S / 256, 256, 0, s1>>>(basis, mixer, wq, wk, wv);

    // main: conv1a  h in [0,16)   (#4 — captured by ncu)
    k_conv_tc<128, 64, 4, 2, true, false>
        <<<dim3(8, 16, 4), 256, SM1>>>(x, wtp1, c1b, hbuf, 0);
    cudaEventRecord(e1a, (cudaStream_t)0);

    k_attn<<<(BATCH * S) / 256, 256, 0, s1>>>(x, wv, alpha, out);
    cudaEventRecord(eA, s1);

    // main: conv1b  h in [16,32)  (#6)
    k_conv_tc<128, 64, 4, 2, true, false>
        <<<dim3(8, 16, 4), 256, SM1>>>(x, wtp1, c1b, hbuf, 16);

    // s2: conv2a  h in [0,14) — needs conv1a output rows <=15, attn-out  (#7)
    cudaStreamWaitEvent(s2, e1a, 0);
    cudaStreamWaitEvent(s2, eA, 0);
    k_conv_tc<64, 32, 8, 1, false, true>
        <<<dim3(4, 14, 4), 256, SM2, s2>>>(hbuf, wtp2, c2b, out, 0);
    cudaEventRecord(e2a, s2);

    // main: conv2b  h in [14,32) — after conv1b (stream order) + attn  (#8)
    cudaStreamWaitEvent((cudaStream_t)0, eA, 0);
    k_conv_tc<64, 32, 8, 1, false, true>
        <<<dim3(4, 18, 4), 256, SM2>>>(hbuf, wtp2, c2b, out, 14);

    // rejoin s2 into origin stream so the captured graph is complete
    cudaStreamWaitEvent((cudaStream_t)0, e2a, 0);
}